// round 14
// baseline (speedup 1.0000x reference)
#include <cuda_runtime.h>
#include <cuda_fp16.h>
#include <math.h>
#include <stdint.h>

#define DIMS 1024
#define FFD  4096
#define BATCH 4
#define SEQ  4096
#define ROWS (BATCH*SEQ)   // 16384
#define NF   513           // rfft bins for N=1024
#define SCHUNK 32

// ---------------- scratch (device globals; no allocation allowed) ----------------
__device__ __half g_qkh[(size_t)ROWS*2*DIMS];
__device__ __half g_x1h[(size_t)ROWS*DIMS];
__device__ __half g_ffh[(size_t)ROWS*DIMS];
__device__ __half g_h  [(size_t)ROWS*FFD];
__device__ __half g_xh [(size_t)ROWS*DIMS];
__device__ __half g_wh [(size_t)(2*DIMS*DIMS + 2*DIMS*FFD)];
__device__ float  g_br [2*DIMS];
__device__ float2 g_kx[(size_t)ROWS*NF];
__device__ float2 g_qf[(size_t)ROWS*NF];
__device__ float2 g_sf[BATCH*NF];
__device__ float2 g_sp[SCHUNK*BATCH*NF];

#define WQK_OFF 0
#define W1_OFF  (2*DIMS*DIMS)
#define W2_OFF  (2*DIMS*DIMS + DIMS*FFD)

// ---------------- PTX helpers ----------------
__device__ __forceinline__ uint32_t smem_u32(const void* p) {
    uint32_t a;
    asm("{ .reg .u64 t; cvta.to.shared.u64 t, %1; cvt.u32.u64 %0, t; }" : "=r"(a) : "l"(p));
    return a;
}
__device__ __forceinline__ uint32_t h2_as_u32(__half2 h) {
    union { __half2 h; uint32_t u; } cvt;
    cvt.h = h;
    return cvt.u;
}
__device__ __forceinline__ void cp16(uint32_t dst, const void* src) {
    asm volatile("cp.async.cg.shared.global [%0], [%1], 16;" :: "r"(dst), "l"(src));
}
#define CP_COMMIT() asm volatile("cp.async.commit_group;" ::: "memory")
template<int N> __device__ __forceinline__ void cp_wait() {
    asm volatile("cp.async.wait_group %0;" :: "n"(N) : "memory");
}
__device__ __forceinline__ void mma_f16(float& c0, float& c1, float& c2, float& c3,
                                        uint32_t a0, uint32_t a1, uint32_t a2, uint32_t a3,
                                        uint32_t b0, uint32_t b1) {
    asm volatile(
        "mma.sync.aligned.m16n8k16.row.col.f32.f16.f16.f32 "
        "{%0,%1,%2,%3}, {%4,%5,%6,%7}, {%8,%9}, {%0,%1,%2,%3};"
        : "+f"(c0), "+f"(c1), "+f"(c2), "+f"(c3)
        : "r"(a0), "r"(a1), "r"(a2), "r"(a3), "r"(b0), "r"(b1));
}
__device__ __forceinline__ void ldsm_x4(uint32_t& r0, uint32_t& r1, uint32_t& r2, uint32_t& r3,
                                        uint32_t addr) {
    asm volatile("ldmatrix.sync.aligned.m8n8.x4.shared.b16 {%0,%1,%2,%3}, [%4];"
                 : "=r"(r0), "=r"(r1), "=r"(r2), "=r"(r3) : "r"(addr));
}

// ---------------- conversion kernels ----------------
__device__ __forceinline__ void conv8(const float* __restrict__ src,
                                      __half* __restrict__ dst, int i) {
    float4 a = ((const float4*)src)[2*i];
    float4 b = ((const float4*)src)[2*i+1];
    uint4 o;
    o.x = h2_as_u32(__floats2half2_rn(a.x, a.y));
    o.y = h2_as_u32(__floats2half2_rn(a.z, a.w));
    o.z = h2_as_u32(__floats2half2_rn(b.x, b.y));
    o.w = h2_as_u32(__floats2half2_rn(b.z, b.w));
    ((uint4*)dst)[i] = o;
}

#define XB   8192
#define WQB  512
#define WKB  512
#define BBLK 8
#define CONVM_BLOCKS (XB + WQB + WKB + BBLK)
__global__ void __launch_bounds__(256) conv_main_kernel(
    const float* __restrict__ x,
    const float* __restrict__ Wq, const float* __restrict__ Wk,
    const float* __restrict__ bq, const float* __restrict__ bk,
    __half* __restrict__ xh, __half* __restrict__ wh)
{
    int bid = blockIdx.x;
    if (bid < XB)            { conv8(x,  xh,                       bid * 256 + threadIdx.x); }
    else if (bid < XB+WQB)   { conv8(Wq, wh + WQK_OFF,             (bid - XB) * 256 + threadIdx.x); }
    else if (bid < XB+WQB+WKB) { conv8(Wk, wh + WQK_OFF + DIMS*DIMS, (bid - XB - WQB) * 256 + threadIdx.x); }
    else {
        int i = (bid - (XB+WQB+WKB)) * 256 + threadIdx.x;
        if (i < DIMS) g_br[i] = bq[i];
        else          g_br[i] = bk[i - DIMS];
    }
}
#define W1B  2048
#define W2B  2048
#define CONVW_BLOCKS (W1B + W2B)
__global__ void __launch_bounds__(256) conv_w_kernel(
    const float* __restrict__ W1, const float* __restrict__ W2,
    __half* __restrict__ wh)
{
    int bid = blockIdx.x;
    if (bid < W1B) conv8(W1, wh + W1_OFF, bid * 256 + threadIdx.x);
    else           conv8(W2, wh + W2_OFF, (bid - W1B) * 256 + threadIdx.x);
}

// ======================= mma.sync fp16 GEMM =======================
#define BK 64
#define ROWB 144
#define A_TILE_BYTES (256*ROWB)
#define B_TILE_BYTES (128*ROWB)
#define STAGE_BYTES (A_TILE_BYTES + B_TILE_BYTES)
#define NSTAGE 4

template<int RELU, typename CT>
__global__ void __launch_bounds__(256, 1)
gemm_h(const __half* __restrict__ A, const __half* __restrict__ B,
       const float* __restrict__ bias, CT* __restrict__ C,
       int N, int K)
{
    extern __shared__ char smem[];
    const int tid = threadIdx.x;
    const int warp = tid >> 5;
    const int lane = tid & 31;
    const int wm = warp >> 1;
    const int wn = warp & 1;
    const int lr = lane >> 2;
    const int lc = lane & 3;

    const __half* Ab = A + (size_t)blockIdx.y * 256 * K;
    const __half* Bb = B + (size_t)blockIdx.x * 128 * K;

    const uint32_t sbase = smem_u32(smem);
    const int ktiles = K / BK;

    uint32_t aoff[4];
    {
        const int l7 = lane & 7;
        const int rsel = (lane >> 3) & 1;
        const int csel = lane >> 4;
        #pragma unroll
        for (int mt = 0; mt < 4; mt++) {
            int r = wm * 64 + mt * 16 + l7 + rsel * 8;
            aoff[mt] = (uint32_t)(r * ROWB + csel * 16);
        }
    }
    uint32_t boff[4];
    {
        const int l7 = lane & 7;
        const int csel = (lane >> 3) & 1;
        const int rsel = lane >> 4;
        #pragma unroll
        for (int pr = 0; pr < 4; pr++) {
            int r = wn * 64 + pr * 16 + rsel * 8 + l7;
            boff[pr] = (uint32_t)(r * ROWB + csel * 16);
        }
    }

    auto load_stage = [&](int stage, int kt) {
        const int k0 = kt * BK;
        const uint32_t sA = sbase + stage * STAGE_BYTES;
        const uint32_t sB = sA + A_TILE_BYTES;
        #pragma unroll
        for (int i = 0; i < 8; i++) {
            int g = i * 256 + tid;
            int r = g >> 3, c = g & 7;
            cp16(sA + r * ROWB + c * 16, Ab + (size_t)r * K + k0 + c * 8);
        }
        #pragma unroll
        for (int i = 0; i < 4; i++) {
            int g = i * 256 + tid;
            int r = g >> 3, c = g & 7;
            cp16(sB + r * ROWB + c * 16, Bb + (size_t)r * K + k0 + c * 8);
        }
    };

    load_stage(0, 0); CP_COMMIT();
    load_stage(1, 1); CP_COMMIT();
    load_stage(2, 2); CP_COMMIT();

    float acc[4][8][4];
    #pragma unroll
    for (int i = 0; i < 4; i++)
        #pragma unroll
        for (int j = 0; j < 8; j++)
            #pragma unroll
            for (int r = 0; r < 4; r++) acc[i][j][r] = 0.f;

    for (int it = 0; it < ktiles; it++) {
        cp_wait<NSTAGE - 2>();
        __syncthreads();

        const uint32_t sA = sbase + (it % NSTAGE) * STAGE_BYTES;
        const uint32_t sB = sA + A_TILE_BYTES;

        const int nt3 = it + NSTAGE - 1;
        if (nt3 < ktiles) load_stage(nt3 % NSTAGE, nt3);
        CP_COMMIT();

        #pragma unroll
        for (int ks = 0; ks < 4; ks++) {
            const uint32_t kb = ks * 32;
            uint32_t a[4][4], b[8][2];
            #pragma unroll
            for (int mt = 0; mt < 4; mt++)
                ldsm_x4(a[mt][0], a[mt][1], a[mt][2], a[mt][3], sA + aoff[mt] + kb);
            #pragma unroll
            for (int pr = 0; pr < 4; pr++)
                ldsm_x4(b[2*pr][0], b[2*pr][1], b[2*pr+1][0], b[2*pr+1][1],
                        sB + boff[pr] + kb);
            #pragma unroll
            for (int mt = 0; mt < 4; mt++)
                #pragma unroll
                for (int nt = 0; nt < 8; nt++)
                    mma_f16(acc[mt][nt][0], acc[mt][nt][1],
                            acc[mt][nt][2], acc[mt][nt][3],
                            a[mt][0], a[mt][1], a[mt][2], a[mt][3],
                            b[nt][0], b[nt][1]);
        }
    }

    const int crow0 = blockIdx.y * 256 + wm * 64;
    const int ccol0 = blockIdx.x * 128 + wn * 64;
    float bb0[8], bb1[8];
    #pragma unroll
    for (int nt = 0; nt < 8; nt++) {
        bb0[nt] = __ldg(bias + ccol0 + nt * 8 + lc * 2);
        bb1[nt] = __ldg(bias + ccol0 + nt * 8 + lc * 2 + 1);
    }
    #pragma unroll
    for (int mt = 0; mt < 4; mt++) {
        #pragma unroll
        for (int nt = 0; nt < 8; nt++) {
            const int r0 = crow0 + mt * 16 + lr;
            const int c0 = ccol0 + nt * 8 + lc * 2;
            float v0 = acc[mt][nt][0] + bb0[nt];
            float v1 = acc[mt][nt][1] + bb1[nt];
            float v2 = acc[mt][nt][2] + bb0[nt];
            float v3 = acc[mt][nt][3] + bb1[nt];
            if (RELU) {
                v0 = fmaxf(v0, 0.f); v1 = fmaxf(v1, 0.f);
                v2 = fmaxf(v2, 0.f); v3 = fmaxf(v3, 0.f);
            }
            if (sizeof(CT) == 2) {
                *(__half2*)((__half*)C + (size_t)r0 * N + c0)       = __floats2half2_rn(v0, v1);
                *(__half2*)((__half*)C + (size_t)(r0 + 8) * N + c0) = __floats2half2_rn(v2, v3);
            } else {
                *(float2*)((float*)C + (size_t)r0 * N + c0)       = make_float2(v0, v1);
                *(float2*)((float*)C + (size_t)(r0 + 8) * N + c0) = make_float2(v2, v3);
            }
        }
    }
}

// ---------------- FFT path helpers ----------------
__device__ __forceinline__ float2 cmulf(float2 a, float2 b) {
    return make_float2(a.x*b.x - a.y*b.y, a.x*b.y + a.y*b.x);
}
// padded shared index: banks spread for strided Stockham writes
#define M(i) ((i) + ((i) >> 4))
#define FBUF 1088   // M(1023)=1086 -> 1088 floats per buffer

template<int NW>
__device__ __forceinline__ float2 block_sum2(float2 v, volatile float2* red) {
    int t = threadIdx.x;
    #pragma unroll
    for (int o = 16; o; o >>= 1) {
        v.x += __shfl_xor_sync(0xffffffffu, v.x, o);
        v.y += __shfl_xor_sync(0xffffffffu, v.y, o);
    }
    if ((t & 31) == 0) { red[t >> 5].x = v.x; red[t >> 5].y = v.y; }
    __syncthreads();
    if (t == 0) {
        float2 s = make_float2(0.f, 0.f);
        #pragma unroll
        for (int i = 0; i < NW; i++) { s.x += red[i].x; s.y += red[i].y; }
        red[0].x = s.x; red[0].y = s.y;
    }
    __syncthreads();
    float2 r = make_float2(red[0].x, red[0].y);
    __syncthreads();
    return r;
}

// 1024-pt radix-4 Stockham FFT (forward), SoA shared, 256 threads, 5 stages.
// Input in (aR,aI), result in (bR,bI). Caller syncs after filling aR/aI via M().
__device__ __forceinline__ void fft1024_soa(float* aR, float* aI, float* bR, float* bI,
                                            const float2* tw, int v) {
    float *sR = aR, *sI = aI, *dR = bR, *dI = bI;
    #pragma unroll
    for (int st = 0; st < 5; st++) {
        const int s = 1 << (2 * st);
        const int idx = v & ~(s - 1);
        float2 w1 = tw[idx];
        float2 w2 = tw[2*idx];
        float2 w3 = tw[3*idx];
        float ax = sR[M(v)],     ay = sI[M(v)];
        float bx = sR[M(v+256)], by = sI[M(v+256)];
        float cx = sR[M(v+512)], cy = sI[M(v+512)];
        float dx = sR[M(v+768)], dy = sI[M(v+768)];
        float apcx = ax + cx, apcy = ay + cy;
        float amcx = ax - cx, amcy = ay - cy;
        float bpdx = bx + dx, bpdy = by + dy;
        float jbx = -(by - dy), jby = bx - dx;    // i*(b-d)
        const int bo = v + 3 * idx;
        dR[M(bo)] = apcx + bpdx;
        dI[M(bo)] = apcy + bpdy;
        float t1x = amcx - jbx, t1y = amcy - jby;
        dR[M(bo + s)]   = t1x*w1.x - t1y*w1.y;
        dI[M(bo + s)]   = t1x*w1.y + t1y*w1.x;
        float t2x = apcx - bpdx, t2y = apcy - bpdy;
        dR[M(bo + 2*s)] = t2x*w2.x - t2y*w2.y;
        dI[M(bo + 2*s)] = t2x*w2.y + t2y*w2.x;
        float t3x = amcx + jbx, t3y = amcy + jby;
        dR[M(bo + 3*s)] = t3x*w3.x - t3y*w3.y;
        dI[M(bo + 3*s)] = t3x*w3.y + t3y*w3.x;
        __syncthreads();
        float* tp;
        tp = sR; sR = dR; dR = tp;
        tp = sI; sI = dI; dI = tp;
    }
}

// ---------------- forward: LN(q,k) x2 rows; 3 FFTs per 2 rows ----------------
__global__ void __launch_bounds__(256) fft_fwd_kernel(
    const float* __restrict__ gq, const float* __restrict__ betaq,
    const float* __restrict__ gk, const float* __restrict__ betak)
{
    const int row0 = blockIdx.x * 2;
    const int row1 = row0 + 1;
    const int t = threadIdx.x;
    __shared__ float2 tw[768];
    __shared__ float aR[FBUF], aI[FBUF], bR[FBUF], bI[FBUF];
    __shared__ float2 red2[8];

    #pragma unroll
    for (int j = 0; j < 3; j++) {
        int i = t + 256 * j;
        float s_, c_;
        sincospif((float)i * (1.0f/512.0f), &s_, &c_);
        tw[i] = make_float2(c_, -s_);
    }

    const float invN = 1.0f / 1024.0f;
    float xv[2][4], qn[2][4], kn[2][4];
    #pragma unroll
    for (int r = 0; r < 2; r++) {
        const int row = row0 + r;
        const __half* xr = g_xh  + (size_t)row * DIMS;
        const __half* qr = g_qkh + (size_t)row * 2 * DIMS;
        const __half* kr = qr + DIMS;
        float qv[4], kv[4];
        #pragma unroll
        for (int i = 0; i < 4; i++) {
            int e = t + 256 * i;
            xv[r][i] = __half2float(xr[e]);
            qv[i] = __half2float(qr[e]);
            kv[i] = __half2float(kr[e]);
        }
        float2 s1 = make_float2(0.f, 0.f), s2 = make_float2(0.f, 0.f);
        #pragma unroll
        for (int i = 0; i < 4; i++) {
            s1.x += qv[i]; s1.y += kv[i];
            s2.x += qv[i]*qv[i]; s2.y += kv[i]*kv[i];
        }
        s1 = block_sum2<8>(s1, red2);
        s2 = block_sum2<8>(s2, red2);
        float mq = s1.x * invN, vq = s2.x * invN - mq*mq;
        float rq = rsqrtf(vq + 1e-5f);
        float mk = s1.y * invN, vk = s2.y * invN - mk*mk;
        float rk = rsqrtf(vk + 1e-5f);
        #pragma unroll
        for (int i = 0; i < 4; i++) {
            int e = t + 256 * i;
            qn[r][i] = (qv[i] - mq) * rq * gq[e] + betaq[e];
            kn[r][i] = (kv[i] - mk) * rk * gk[e] + betak[e];
        }
    }

    // FFT of x_r + i*kn_r -> Kx row r
    #pragma unroll
    for (int r = 0; r < 2; r++) {
        const int row = row0 + r;
        #pragma unroll
        for (int i = 0; i < 4; i++) {
            int e = t + 256 * i;
            aR[M(e)] = xv[r][i];
            aI[M(e)] = kn[r][i];
        }
        __syncthreads();
        fft1024_soa(aR, aI, bR, bI, tw, t);
        #pragma unroll
        for (int jj = 0; jj < 2; jj++) {
            int j = t + 256 * jj;
            int jn = (1024 - j) & 1023;
            float zx = bR[M(j)],  zy = bI[M(j)];
            float nx = bR[M(jn)], ny = bI[M(jn)];
            float2 xf = make_float2(0.5f*(zx + nx), 0.5f*(zy - ny));
            float dfx = zx - nx, dfy = zy + ny;
            float2 kf = make_float2(0.5f*dfy, -0.5f*dfx);
            g_kx[(size_t)row*NF + j] = cmulf(xf, kf);
        }
        if (t == 0) {
            g_kx[(size_t)row*NF + 512] = make_float2(bR[M(512)] * bI[M(512)], 0.f);
        }
        __syncthreads();
    }

    // FFT of qn0 + i*qn1 -> Qf rows row0, row1
    #pragma unroll
    for (int i = 0; i < 4; i++) {
        int e = t + 256 * i;
        aR[M(e)] = qn[0][i];
        aI[M(e)] = qn[1][i];
    }
    __syncthreads();
    fft1024_soa(aR, aI, bR, bI, tw, t);
    #pragma unroll
    for (int jj = 0; jj < 2; jj++) {
        int j = t + 256 * jj;
        int jn = (1024 - j) & 1023;
        float zx = bR[M(j)],  zy = bI[M(j)];
        float nx = bR[M(jn)], ny = bI[M(jn)];
        float2 q0 = make_float2(0.5f*(zx + nx), 0.5f*(zy - ny));
        float dfx = zx - nx, dfy = zy + ny;
        float2 q1 = make_float2(0.5f*dfy, -0.5f*dfx);
        g_qf[(size_t)row0*NF + j] = q0;
        g_qf[(size_t)row1*NF + j] = q1;
    }
    if (t == 0) {
        g_qf[(size_t)row0*NF + 512] = make_float2(bR[M(512)], 0.f);
        g_qf[(size_t)row1*NF + 512] = make_float2(bI[M(512)], 0.f);
    }
}

// ---------------- reduce S stage 1 + 2 ----------------
__global__ void __launch_bounds__(256) reduce_s1_kernel() {
    const int b  = blockIdx.x;
    const int jc = blockIdx.y;
    const int sc = blockIdx.z;
    const int t  = threadIdx.x;
    const int jl = t & 63;
    const int sl = t >> 6;
    const int j  = jc * 64 + jl;
    float2 acc = make_float2(0.f, 0.f);
    if (j < NF) {
        const int s0 = sc * 128;
        const float2* p = g_kx + (size_t)b * SEQ * NF + (size_t)s0 * NF + j;
        for (int s = sl; s < 128; s += 4) {
            float2 v = p[(size_t)s * NF];
            acc.x += v.x; acc.y += v.y;
        }
    }
    __shared__ float2 red[256];
    red[t] = acc;
    __syncthreads();
    if (t < 128) { red[t].x += red[t+128].x; red[t].y += red[t+128].y; }
    __syncthreads();
    if (t < 64) {
        red[t].x += red[t+64].x; red[t].y += red[t+64].y;
        if (j < NF) g_sp[((size_t)sc * BATCH + b) * NF + j] = red[t];
    }
}
__global__ void __launch_bounds__(64) reduce_s2_kernel() {
    const int b  = blockIdx.x;
    const int jc = blockIdx.y;
    const int j  = jc * 64 + threadIdx.x;
    if (j >= NF) return;
    float2 acc = make_float2(0.f, 0.f);
    #pragma unroll
    for (int sc = 0; sc < SCHUNK; sc++) {
        float2 v = g_sp[((size_t)sc * BATCH + b) * NF + j];
        acc.x += v.x; acc.y += v.y;
    }
    g_sf[b * NF + j] = acc;
}

// ---------------- inverse: 1 FFT per 2 rows; LN(x+mix) x2 -> fp16 x1 ----------------
__global__ void __launch_bounds__(256) fft_inv_ln_kernel(
    const float* __restrict__ g0, const float* __restrict__ beta0)
{
    const int row0 = blockIdx.x * 2;
    const int row1 = row0 + 1;
    const int b = row0 >> 12;
    const int t = threadIdx.x;
    __shared__ float2 tw[768];
    __shared__ float aR[FBUF], aI[FBUF], bR[FBUF], bI[FBUF];
    __shared__ float2 red2[8];

    #pragma unroll
    for (int j = 0; j < 3; j++) {
        int i = t + 256 * j;
        float s_, c_;
        sincospif((float)i * (1.0f/512.0f), &s_, &c_);
        tw[i] = make_float2(c_, -s_);
    }

    #pragma unroll
    for (int jj = 0; jj < 2; jj++) {
        int j = t + 256 * jj;
        float2 sf = g_sf[b*NF + j];
        float2 kx0 = g_kx[(size_t)row0*NF + j];
        float2 qf0 = g_qf[(size_t)row0*NF + j];
        float2 m0 = make_float2(kx0.x + sf.x*qf0.x + sf.y*qf0.y,
                                kx0.y - sf.x*qf0.y + sf.y*qf0.x);
        float2 kx1 = g_kx[(size_t)row1*NF + j];
        float2 qf1 = g_qf[(size_t)row1*NF + j];
        float2 m1 = make_float2(kx1.x + sf.x*qf1.x + sf.y*qf1.y,
                                kx1.y - sf.x*qf1.y + sf.y*qf1.x);
        // bufA[j] = conj(M0) - i*conj(M1)
        aR[M(j)] = m0.x - m1.y;
        aI[M(j)] = -m0.y - m1.x;
        if (j > 0) {
            int jm = 1024 - j;
            aR[M(jm)] = m0.x + m1.y;
            aI[M(jm)] = m0.y - m1.x;
        }
    }
    if (t == 0) {
        float2 sf = g_sf[b*NF + 512];
        float2 kx0 = g_kx[(size_t)row0*NF + 512];
        float2 qf0 = g_qf[(size_t)row0*NF + 512];
        float m0 = kx0.x + sf.x*qf0.x;
        float2 kx1 = g_kx[(size_t)row1*NF + 512];
        float2 qf1 = g_qf[(size_t)row1*NF + 512];
        float m1 = kx1.x + sf.x*qf1.x;
        aR[M(512)] = m0;
        aI[M(512)] = -m1;
    }
    __syncthreads();
    fft1024_soa(aR, aI, bR, bI, tw, t);
    // y0 = Re(W)/N ; y1 = -Im(W)/N

    const float invN = 1.0f / 1024.0f;
    #pragma unroll
    for (int r = 0; r < 2; r++) {
        const int row = row0 + r;
        const __half* xr = g_xh + (size_t)row * DIMS;
        float y[4];
        float2 s12 = make_float2(0.f, 0.f);
        #pragma unroll
        for (int i = 0; i < 4; i++) {
            int e = t + 256 * i;
            float wv = (r == 0) ? bR[M(e)] : -bI[M(e)];
            y[i] = __half2float(xr[e]) + wv * invN;
            s12.x += y[i];
            s12.y += y[i] * y[i];
        }
        s12 = block_sum2<8>(s12, red2);
        float m = s12.x * invN, v = s12.y * invN - m*m;
        float rr = rsqrtf(v + 1e-5f);
        __half* oh = g_x1h + (size_t)row * DIMS;
        #pragma unroll
        for (int i = 0; i < 4; i++) {
            int e = t + 256 * i;
            float ov = (y[i] - m) * rr * g0[e] + beta0[e];
            oh[e] = __float2half_rn(ov);
        }
    }
}

// ---------------- out = LN(x1 + ff)  (fp16 in, fused paired reduction) ----------------
__global__ void __launch_bounds__(512) resid_ln_kernel(
    const float* __restrict__ g1v, const float* __restrict__ beta1,
    float* __restrict__ out)
{
    const int row = blockIdx.x;
    const int t = threadIdx.x;
    __shared__ float2 red2[16];
    const __half2* a = (const __half2*)(g_x1h + (size_t)row * DIMS);
    const __half2* f = (const __half2*)(g_ffh + (size_t)row * DIMS);
    float2 av = __half22float2(a[t]);
    float2 fv = __half22float2(f[t]);
    float y0 = av.x + fv.x;
    float y1 = av.y + fv.y;
    const float invN = 1.0f / 1024.0f;
    float2 s12 = block_sum2<16>(make_float2(y0 + y1, y0*y0 + y1*y1), red2);
    float m = s12.x * invN, v = s12.y * invN - m*m;
    float r = rsqrtf(v + 1e-5f);
    float* o = out + (size_t)row * DIMS;
    o[2*t]   = (y0 - m) * r * g1v[2*t]   + beta1[2*t];
    o[2*t+1] = (y1 - m) * r * g1v[2*t+1] + beta1[2*t+1];
}

// ---------------- launch ----------------
extern "C" void kernel_launch(void* const* d_in, const int* in_sizes, int n_in,
                              void* d_out, int out_size)
{
    const float* x     = (const float*)d_in[0];
    const float* Wq    = (const float*)d_in[1];
    const float* bq    = (const float*)d_in[2];
    const float* gq    = (const float*)d_in[3];
    const float* betaq = (const float*)d_in[4];
    const float* Wk    = (const float*)d_in[5];
    const float* bk    = (const float*)d_in[6];
    const float* gk    = (const float*)d_in[7];
    const float* betak = (const float*)d_in[8];
    const float* g0    = (const float*)d_in[9];
    const float* beta0 = (const float*)d_in[10];
    const float* W1    = (const float*)d_in[11];
    const float* b1    = (const float*)d_in[12];
    const float* W2    = (const float*)d_in[13];
    const float* b2    = (const float*)d_in[14];
    const float* g1    = (const float*)d_in[15];
    const float* beta1 = (const float*)d_in[16];
    float* out = (float*)d_out;

    float *pbr;
    __half *pqkh, *px1h, *ph, *pxh, *pwh, *pffh;
    cudaGetSymbolAddress((void**)&pqkh, g_qkh);
    cudaGetSymbolAddress((void**)&px1h, g_x1h);
    cudaGetSymbolAddress((void**)&ph,   g_h);
    cudaGetSymbolAddress((void**)&pffh, g_ffh);
    cudaGetSymbolAddress((void**)&pxh,  g_xh);
    cudaGetSymbolAddress((void**)&pwh,  g_wh);
    cudaGetSymbolAddress((void**)&pbr,  g_br);

    const int SMEM = NSTAGE * STAGE_BYTES;  // 221184 B
    cudaFuncSetAttribute(gemm_h<0,__half>, cudaFuncAttributeMaxDynamicSharedMemorySize, SMEM);
    cudaFuncSetAttribute(gemm_h<1,__half>, cudaFuncAttributeMaxDynamicSharedMemorySize, SMEM);

    // fork: aux stream converts W1/W2 concurrently with G1
    cudaStream_t s1;
    cudaStreamCreate(&s1);
    cudaEvent_t eFork, eW;
    cudaEventCreateWithFlags(&eFork, cudaEventDisableTiming);
    cudaEventCreateWithFlags(&eW,    cudaEventDisableTiming);

    cudaEventRecord(eFork, 0);
    cudaStreamWaitEvent(s1, eFork, 0);
    conv_w_kernel<<<CONVW_BLOCKS, 256, 0, s1>>>(W1, W2, pwh);
    cudaEventRecord(eW, s1);

    // main: x/Wq/Wk conversion + bias pack
    conv_main_kernel<<<CONVM_BLOCKS, 256>>>(x, Wq, Wk, bq, bk, pxh, pwh);

    // [q|k] = x @ [Wq|Wk]^T + [bq|bk]
    gemm_h<0,__half><<<dim3(2*DIMS/128, ROWS/256), 256, SMEM>>>(pxh, pwh + WQK_OFF, pbr, pqkh, 2*DIMS, DIMS);
    // LN(q), LN(k), forward FFTs (SoA, conflict-reduced)
    fft_fwd_kernel<<<ROWS/2, 256>>>(gq, betaq, gk, betak);
    // S = sum_s Kx (two-stage)
    reduce_s1_kernel<<<dim3(BATCH, 9, SCHUNK), 256>>>();
    reduce_s2_kernel<<<dim3(BATCH, 9), 64>>>();
    // mix = irfft x2 rows; x1 = LN(x + mix) -> fp16
    fft_inv_ln_kernel<<<ROWS/2, 256>>>(g0, beta0);
    // h = relu(x1 @ W1^T + b1)
    cudaStreamWaitEvent(0, eW, 0);
    gemm_h<1,__half><<<dim3(FFD/128, ROWS/256), 256, SMEM>>>(px1h, pwh + W1_OFF, b1, ph, FFD, DIMS);
    // ff = h @ W2^T + b2 -> fp16
    gemm_h<0,__half><<<dim3(DIMS/128, ROWS/256), 256, SMEM>>>(ph, pwh + W2_OFF, b2, pffh, DIMS, FFD);
    // out = LN(x1 + ff)
    resid_ln_kernel<<<ROWS, 512>>>(g1, beta1, out);
}

// round 15
// speedup vs baseline: 1.0251x; 1.0251x over previous
#include <cuda_runtime.h>
#include <cuda_fp16.h>
#include <math.h>
#include <stdint.h>

#define DIMS 1024
#define FFD  4096
#define BATCH 4
#define SEQ  4096
#define ROWS (BATCH*SEQ)   // 16384
#define NF   513           // rfft bins for N=1024
#define SCHUNK 32

// ---------------- scratch (device globals; no allocation allowed) ----------------
__device__ __half g_qkh[(size_t)ROWS*2*DIMS];
__device__ __half g_x1h[(size_t)ROWS*DIMS];
__device__ __half g_ffh[(size_t)ROWS*DIMS];
__device__ __half g_h  [(size_t)ROWS*FFD];
__device__ __half g_xh [(size_t)ROWS*DIMS];
__device__ __half g_wh [(size_t)(2*DIMS*DIMS + 2*DIMS*FFD)];
__device__ float  g_br [2*DIMS];
__device__ float2 g_kx[(size_t)ROWS*NF];
__device__ float2 g_qf[(size_t)ROWS*NF];
__device__ float2 g_sf[BATCH*NF];
__device__ float2 g_sp[SCHUNK*BATCH*NF];

#define WQK_OFF 0
#define W1_OFF  (2*DIMS*DIMS)
#define W2_OFF  (2*DIMS*DIMS + DIMS*FFD)

// ---------------- PTX helpers ----------------
__device__ __forceinline__ uint32_t smem_u32(const void* p) {
    uint32_t a;
    asm("{ .reg .u64 t; cvta.to.shared.u64 t, %1; cvt.u32.u64 %0, t; }" : "=r"(a) : "l"(p));
    return a;
}
__device__ __forceinline__ uint32_t h2_as_u32(__half2 h) {
    union { __half2 h; uint32_t u; } cvt;
    cvt.h = h;
    return cvt.u;
}
__device__ __forceinline__ void cp16(uint32_t dst, const void* src) {
    asm volatile("cp.async.cg.shared.global [%0], [%1], 16;" :: "r"(dst), "l"(src));
}
#define CP_COMMIT() asm volatile("cp.async.commit_group;" ::: "memory")
template<int N> __device__ __forceinline__ void cp_wait() {
    asm volatile("cp.async.wait_group %0;" :: "n"(N) : "memory");
}
__device__ __forceinline__ void mma_f16(float& c0, float& c1, float& c2, float& c3,
                                        uint32_t a0, uint32_t a1, uint32_t a2, uint32_t a3,
                                        uint32_t b0, uint32_t b1) {
    asm volatile(
        "mma.sync.aligned.m16n8k16.row.col.f32.f16.f16.f32 "
        "{%0,%1,%2,%3}, {%4,%5,%6,%7}, {%8,%9}, {%0,%1,%2,%3};"
        : "+f"(c0), "+f"(c1), "+f"(c2), "+f"(c3)
        : "r"(a0), "r"(a1), "r"(a2), "r"(a3), "r"(b0), "r"(b1));
}
__device__ __forceinline__ void ldsm_x4(uint32_t& r0, uint32_t& r1, uint32_t& r2, uint32_t& r3,
                                        uint32_t addr) {
    asm volatile("ldmatrix.sync.aligned.m8n8.x4.shared.b16 {%0,%1,%2,%3}, [%4];"
                 : "=r"(r0), "=r"(r1), "=r"(r2), "=r"(r3) : "r"(addr));
}

// ---------------- conversion kernels ----------------
__device__ __forceinline__ void conv8(const float* __restrict__ src,
                                      __half* __restrict__ dst, int i) {
    float4 a = ((const float4*)src)[2*i];
    float4 b = ((const float4*)src)[2*i+1];
    uint4 o;
    o.x = h2_as_u32(__floats2half2_rn(a.x, a.y));
    o.y = h2_as_u32(__floats2half2_rn(a.z, a.w));
    o.z = h2_as_u32(__floats2half2_rn(b.x, b.y));
    o.w = h2_as_u32(__floats2half2_rn(b.z, b.w));
    ((uint4*)dst)[i] = o;
}

#define XB   8192
#define WQB  512
#define WKB  512
#define BBLK 8
#define CONVM_BLOCKS (XB + WQB + WKB + BBLK)
__global__ void __launch_bounds__(256) conv_main_kernel(
    const float* __restrict__ x,
    const float* __restrict__ Wq, const float* __restrict__ Wk,
    const float* __restrict__ bq, const float* __restrict__ bk,
    __half* __restrict__ xh, __half* __restrict__ wh)
{
    int bid = blockIdx.x;
    if (bid < XB)            { conv8(x,  xh,                       bid * 256 + threadIdx.x); }
    else if (bid < XB+WQB)   { conv8(Wq, wh + WQK_OFF,             (bid - XB) * 256 + threadIdx.x); }
    else if (bid < XB+WQB+WKB) { conv8(Wk, wh + WQK_OFF + DIMS*DIMS, (bid - XB - WQB) * 256 + threadIdx.x); }
    else {
        int i = (bid - (XB+WQB+WKB)) * 256 + threadIdx.x;
        if (i < DIMS) g_br[i] = bq[i];
        else          g_br[i] = bk[i - DIMS];
    }
}
#define W1B  2048
#define W2B  2048
#define CONVW_BLOCKS (W1B + W2B)
__global__ void __launch_bounds__(256) conv_w_kernel(
    const float* __restrict__ W1, const float* __restrict__ W2,
    __half* __restrict__ wh)
{
    int bid = blockIdx.x;
    if (bid < W1B) conv8(W1, wh + W1_OFF, bid * 256 + threadIdx.x);
    else           conv8(W2, wh + W2_OFF, (bid - W1B) * 256 + threadIdx.x);
}

// ======================= mma.sync fp16 GEMM =======================
#define BK 64
#define ROWB 144
#define A_TILE_BYTES (256*ROWB)
#define B_TILE_BYTES (128*ROWB)
#define STAGE_BYTES (A_TILE_BYTES + B_TILE_BYTES)
#define NSTAGE 4

template<int RELU, typename CT>
__global__ void __launch_bounds__(256, 1)
gemm_h(const __half* __restrict__ A, const __half* __restrict__ B,
       const float* __restrict__ bias, CT* __restrict__ C,
       int N, int K)
{
    extern __shared__ char smem[];
    const int tid = threadIdx.x;
    const int warp = tid >> 5;
    const int lane = tid & 31;
    const int wm = warp >> 1;
    const int wn = warp & 1;
    const int lr = lane >> 2;
    const int lc = lane & 3;

    const __half* Ab = A + (size_t)blockIdx.y * 256 * K;
    const __half* Bb = B + (size_t)blockIdx.x * 128 * K;

    const uint32_t sbase = smem_u32(smem);
    const int ktiles = K / BK;

    uint32_t aoff[4];
    {
        const int l7 = lane & 7;
        const int rsel = (lane >> 3) & 1;
        const int csel = lane >> 4;
        #pragma unroll
        for (int mt = 0; mt < 4; mt++) {
            int r = wm * 64 + mt * 16 + l7 + rsel * 8;
            aoff[mt] = (uint32_t)(r * ROWB + csel * 16);
        }
    }
    uint32_t boff[4];
    {
        const int l7 = lane & 7;
        const int csel = (lane >> 3) & 1;
        const int rsel = lane >> 4;
        #pragma unroll
        for (int pr = 0; pr < 4; pr++) {
            int r = wn * 64 + pr * 16 + rsel * 8 + l7;
            boff[pr] = (uint32_t)(r * ROWB + csel * 16);
        }
    }

    auto load_stage = [&](int stage, int kt) {
        const int k0 = kt * BK;
        const uint32_t sA = sbase + stage * STAGE_BYTES;
        const uint32_t sB = sA + A_TILE_BYTES;
        #pragma unroll
        for (int i = 0; i < 8; i++) {
            int g = i * 256 + tid;
            int r = g >> 3, c = g & 7;
            cp16(sA + r * ROWB + c * 16, Ab + (size_t)r * K + k0 + c * 8);
        }
        #pragma unroll
        for (int i = 0; i < 4; i++) {
            int g = i * 256 + tid;
            int r = g >> 3, c = g & 7;
            cp16(sB + r * ROWB + c * 16, Bb + (size_t)r * K + k0 + c * 8);
        }
    };

    load_stage(0, 0); CP_COMMIT();
    load_stage(1, 1); CP_COMMIT();
    load_stage(2, 2); CP_COMMIT();

    float acc[4][8][4];
    #pragma unroll
    for (int i = 0; i < 4; i++)
        #pragma unroll
        for (int j = 0; j < 8; j++)
            #pragma unroll
            for (int r = 0; r < 4; r++) acc[i][j][r] = 0.f;

    for (int it = 0; it < ktiles; it++) {
        cp_wait<NSTAGE - 2>();
        __syncthreads();

        const uint32_t sA = sbase + (it % NSTAGE) * STAGE_BYTES;
        const uint32_t sB = sA + A_TILE_BYTES;

        const int nt3 = it + NSTAGE - 1;
        if (nt3 < ktiles) load_stage(nt3 % NSTAGE, nt3);
        CP_COMMIT();

        #pragma unroll
        for (int ks = 0; ks < 4; ks++) {
            const uint32_t kb = ks * 32;
            uint32_t a[4][4], b[8][2];
            #pragma unroll
            for (int mt = 0; mt < 4; mt++)
                ldsm_x4(a[mt][0], a[mt][1], a[mt][2], a[mt][3], sA + aoff[mt] + kb);
            #pragma unroll
            for (int pr = 0; pr < 4; pr++)
                ldsm_x4(b[2*pr][0], b[2*pr][1], b[2*pr+1][0], b[2*pr+1][1],
                        sB + boff[pr] + kb);
            #pragma unroll
            for (int mt = 0; mt < 4; mt++)
                #pragma unroll
                for (int nt = 0; nt < 8; nt++)
                    mma_f16(acc[mt][nt][0], acc[mt][nt][1],
                            acc[mt][nt][2], acc[mt][nt][3],
                            a[mt][0], a[mt][1], a[mt][2], a[mt][3],
                            b[nt][0], b[nt][1]);
        }
    }

    const int crow0 = blockIdx.y * 256 + wm * 64;
    const int ccol0 = blockIdx.x * 128 + wn * 64;
    float bb0[8], bb1[8];
    #pragma unroll
    for (int nt = 0; nt < 8; nt++) {
        bb0[nt] = __ldg(bias + ccol0 + nt * 8 + lc * 2);
        bb1[nt] = __ldg(bias + ccol0 + nt * 8 + lc * 2 + 1);
    }
    #pragma unroll
    for (int mt = 0; mt < 4; mt++) {
        #pragma unroll
        for (int nt = 0; nt < 8; nt++) {
            const int r0 = crow0 + mt * 16 + lr;
            const int c0 = ccol0 + nt * 8 + lc * 2;
            float v0 = acc[mt][nt][0] + bb0[nt];
            float v1 = acc[mt][nt][1] + bb1[nt];
            float v2 = acc[mt][nt][2] + bb0[nt];
            float v3 = acc[mt][nt][3] + bb1[nt];
            if (RELU) {
                v0 = fmaxf(v0, 0.f); v1 = fmaxf(v1, 0.f);
                v2 = fmaxf(v2, 0.f); v3 = fmaxf(v3, 0.f);
            }
            if (sizeof(CT) == 2) {
                *(__half2*)((__half*)C + (size_t)r0 * N + c0)       = __floats2half2_rn(v0, v1);
                *(__half2*)((__half*)C + (size_t)(r0 + 8) * N + c0) = __floats2half2_rn(v2, v3);
            } else {
                *(float2*)((float*)C + (size_t)r0 * N + c0)       = make_float2(v0, v1);
                *(float2*)((float*)C + (size_t)(r0 + 8) * N + c0) = make_float2(v2, v3);
            }
        }
    }
}

// ---------------- FFT path helpers ----------------
__device__ __forceinline__ float2 cmulf(float2 a, float2 b) {
    return make_float2(a.x*b.x - a.y*b.y, a.x*b.y + a.y*b.x);
}
#define F(i) ((i) ^ ((((i) >> 5) & 7) << 2))

template<int NW>
__device__ __forceinline__ float2 block_sum2(float2 v, volatile float2* red) {
    int t = threadIdx.x;
    #pragma unroll
    for (int o = 16; o; o >>= 1) {
        v.x += __shfl_xor_sync(0xffffffffu, v.x, o);
        v.y += __shfl_xor_sync(0xffffffffu, v.y, o);
    }
    if ((t & 31) == 0) { red[t >> 5].x = v.x; red[t >> 5].y = v.y; }
    __syncthreads();
    if (t == 0) {
        float2 s = make_float2(0.f, 0.f);
        #pragma unroll
        for (int i = 0; i < NW; i++) { s.x += red[i].x; s.y += red[i].y; }
        red[0].x = s.x; red[0].y = s.y;
    }
    __syncthreads();
    float2 r = make_float2(red[0].x, red[0].y);
    __syncthreads();
    return r;
}

// 1024-pt radix-4 Stockham FFT (forward), 256 threads, 5 stages. Result in bufB.
__device__ __forceinline__ void fft1024_r4(float2* bufA, float2* bufB,
                                           const float2* tw, int v) {
    float2* src = bufA; float2* dst = bufB;
    #pragma unroll
    for (int st = 0; st < 5; st++) {
        const int s = 1 << (2 * st);
        const int idx = v & ~(s - 1);
        float2 w1 = tw[idx];
        float2 w2 = tw[2*idx];
        float2 w3 = tw[3*idx];
        float2 a = src[F(v)];
        float2 b = src[F(v + 256)];
        float2 c = src[F(v + 512)];
        float2 d = src[F(v + 768)];
        float2 apc = make_float2(a.x + c.x, a.y + c.y);
        float2 amc = make_float2(a.x - c.x, a.y - c.y);
        float2 bpd = make_float2(b.x + d.x, b.y + d.y);
        float2 jbmd = make_float2(-(b.y - d.y), b.x - d.x);
        const int bo = v + 3 * idx;
        dst[F(bo)]         = make_float2(apc.x + bpd.x, apc.y + bpd.y);
        dst[F(bo + s)]     = cmulf(w1, make_float2(amc.x - jbmd.x, amc.y - jbmd.y));
        dst[F(bo + 2*s)]   = cmulf(w2, make_float2(apc.x - bpd.x, apc.y - bpd.y));
        dst[F(bo + 3*s)]   = cmulf(w3, make_float2(amc.x + jbmd.x, amc.y + jbmd.y));
        __syncthreads();
        float2* tmp = src; src = dst; dst = tmp;
    }
}

// ---------------- forward: LN stats, then re-read + FFT (low-register) ----------------
__global__ void __launch_bounds__(256) fft_fwd_kernel(
    const float* __restrict__ gq, const float* __restrict__ betaq,
    const float* __restrict__ gk, const float* __restrict__ betak)
{
    const int row0 = blockIdx.x * 2;
    const int t = threadIdx.x;
    __shared__ float2 tw[768];
    __shared__ float2 bufA[1024];
    __shared__ float2 bufB[1024];
    __shared__ float2 red2[8];

    #pragma unroll
    for (int j = 0; j < 3; j++) {
        int i = t + 256 * j;
        float s_, c_;
        sincospif((float)i * (1.0f/512.0f), &s_, &c_);
        tw[i] = make_float2(c_, -s_);
    }

    const float invN = 1.0f / 1024.0f;
    // phase 1: LN stats only (8 persistent regs)
    float mq[2], rq[2], mk[2], rk[2];
    #pragma unroll
    for (int r = 0; r < 2; r++) {
        const __half* qr = g_qkh + (size_t)(row0 + r) * 2 * DIMS;
        const __half* kr = qr + DIMS;
        float2 s1 = make_float2(0.f, 0.f), s2 = make_float2(0.f, 0.f);
        #pragma unroll
        for (int i = 0; i < 4; i++) {
            int e = t + 256 * i;
            float qv = __half2float(qr[e]);
            float kv = __half2float(kr[e]);
            s1.x += qv; s1.y += kv;
            s2.x += qv*qv; s2.y += kv*kv;
        }
        s1 = block_sum2<8>(s1, red2);
        s2 = block_sum2<8>(s2, red2);
        mq[r] = s1.x * invN;
        rq[r] = rsqrtf(s2.x * invN - mq[r]*mq[r] + 1e-5f);
        mk[r] = s1.y * invN;
        rk[r] = rsqrtf(s2.y * invN - mk[r]*mk[r] + 1e-5f);
    }

    // phase 2: FFT of x_r + i*LN(k_r) -> Kx row r  (re-read x,k; LN on the fly)
    #pragma unroll
    for (int r = 0; r < 2; r++) {
        const int row = row0 + r;
        const __half* xr = g_xh  + (size_t)row * DIMS;
        const __half* kr = g_qkh + (size_t)row * 2 * DIMS + DIMS;
        #pragma unroll
        for (int i = 0; i < 4; i++) {
            int e = t + 256 * i;
            float kn = (__half2float(kr[e]) - mk[r]) * rk[r] * gk[e] + betak[e];
            bufA[F(e)] = make_float2(__half2float(xr[e]), kn);
        }
        __syncthreads();
        fft1024_r4(bufA, bufB, tw, t);
        #pragma unroll
        for (int jj = 0; jj < 2; jj++) {
            int j = t + 256 * jj;
            float2 z  = bufB[F(j)];
            float2 zn = bufB[F((1024 - j) & 1023)];
            float2 xf = make_float2(0.5f*(z.x + zn.x), 0.5f*(z.y - zn.y));
            float2 df = make_float2(z.x - zn.x, z.y + zn.y);
            float2 kf = make_float2(0.5f*df.y, -0.5f*df.x);
            g_kx[(size_t)row*NF + j] = cmulf(xf, kf);
        }
        if (t == 0) {
            float2 z5 = bufB[F(512)];
            g_kx[(size_t)row*NF + 512] = make_float2(z5.x * z5.y, 0.f);
        }
        __syncthreads();
    }

    // phase 3: FFT of LN(q_0) + i*LN(q_1) -> Qf rows (re-read q; LN on the fly)
    {
        const __half* q0r = g_qkh + (size_t)row0 * 2 * DIMS;
        const __half* q1r = q0r + 2 * DIMS;
        #pragma unroll
        for (int i = 0; i < 4; i++) {
            int e = t + 256 * i;
            float ge = gq[e], be = betaq[e];
            float q0 = (__half2float(q0r[e]) - mq[0]) * rq[0] * ge + be;
            float q1 = (__half2float(q1r[e]) - mq[1]) * rq[1] * ge + be;
            bufA[F(e)] = make_float2(q0, q1);
        }
    }
    __syncthreads();
    fft1024_r4(bufA, bufB, tw, t);
    #pragma unroll
    for (int jj = 0; jj < 2; jj++) {
        int j = t + 256 * jj;
        float2 z  = bufB[F(j)];
        float2 zn = bufB[F((1024 - j) & 1023)];
        float2 q0 = make_float2(0.5f*(z.x + zn.x), 0.5f*(z.y - zn.y));
        float2 df = make_float2(z.x - zn.x, z.y + zn.y);
        float2 q1 = make_float2(0.5f*df.y, -0.5f*df.x);
        g_qf[(size_t)row0*NF + j]     = q0;
        g_qf[(size_t)(row0+1)*NF + j] = q1;
    }
    if (t == 0) {
        float2 z5 = bufB[F(512)];
        g_qf[(size_t)row0*NF + 512]     = make_float2(z5.x, 0.f);
        g_qf[(size_t)(row0+1)*NF + 512] = make_float2(z5.y, 0.f);
    }
}

// ---------------- reduce S stage 1 + 2 ----------------
__global__ void __launch_bounds__(256) reduce_s1_kernel() {
    const int b  = blockIdx.x;
    const int jc = blockIdx.y;
    const int sc = blockIdx.z;
    const int t  = threadIdx.x;
    const int jl = t & 63;
    const int sl = t >> 6;
    const int j  = jc * 64 + jl;
    float2 acc = make_float2(0.f, 0.f);
    if (j < NF) {
        const int s0 = sc * 128;
        const float2* p = g_kx + (size_t)b * SEQ * NF + (size_t)s0 * NF + j;
        for (int s = sl; s < 128; s += 4) {
            float2 v = p[(size_t)s * NF];
            acc.x += v.x; acc.y += v.y;
        }
    }
    __shared__ float2 red[256];
    red[t] = acc;
    __syncthreads();
    if (t < 128) { red[t].x += red[t+128].x; red[t].y += red[t+128].y; }
    __syncthreads();
    if (t < 64) {
        red[t].x += red[t+64].x; red[t].y += red[t+64].y;
        if (j < NF) g_sp[((size_t)sc * BATCH + b) * NF + j] = red[t];
    }
}
__global__ void __launch_bounds__(64) reduce_s2_kernel() {
    const int b  = blockIdx.x;
    const int jc = blockIdx.y;
    const int j  = jc * 64 + threadIdx.x;
    if (j >= NF) return;
    float2 acc = make_float2(0.f, 0.f);
    #pragma unroll
    for (int sc = 0; sc < SCHUNK; sc++) {
        float2 v = g_sp[((size_t)sc * BATCH + b) * NF + j];
        acc.x += v.x; acc.y += v.y;
    }
    g_sf[b * NF + j] = acc;
}

// ---------------- inverse: 1 FFT per 2 rows; LN(x+mix) x2 -> fp16 x1 ----------------
__global__ void __launch_bounds__(256) fft_inv_ln_kernel(
    const float* __restrict__ g0, const float* __restrict__ beta0)
{
    const int row0 = blockIdx.x * 2;
    const int row1 = row0 + 1;
    const int b = row0 >> 12;
    const int t = threadIdx.x;
    __shared__ float2 tw[768];
    __shared__ float2 bufA[1024];
    __shared__ float2 bufB[1024];
    __shared__ float2 red2[8];

    #pragma unroll
    for (int j = 0; j < 3; j++) {
        int i = t + 256 * j;
        float s_, c_;
        sincospif((float)i * (1.0f/512.0f), &s_, &c_);
        tw[i] = make_float2(c_, -s_);
    }

    #pragma unroll
    for (int jj = 0; jj < 2; jj++) {
        int j = t + 256 * jj;
        float2 sf = g_sf[b*NF + j];
        float2 kx0 = g_kx[(size_t)row0*NF + j];
        float2 qf0 = g_qf[(size_t)row0*NF + j];
        float2 m0 = make_float2(kx0.x + sf.x*qf0.x + sf.y*qf0.y,
                                kx0.y - sf.x*qf0.y + sf.y*qf0.x);
        float2 kx1 = g_kx[(size_t)row1*NF + j];
        float2 qf1 = g_qf[(size_t)row1*NF + j];
        float2 m1 = make_float2(kx1.x + sf.x*qf1.x + sf.y*qf1.y,
                                kx1.y - sf.x*qf1.y + sf.y*qf1.x);
        bufA[F(j)] = make_float2(m0.x - m1.y, -m0.y - m1.x);
        if (j > 0) bufA[F(1024 - j)] = make_float2(m0.x + m1.y, m0.y - m1.x);
    }
    if (t == 0) {
        float2 sf = g_sf[b*NF + 512];
        float2 kx0 = g_kx[(size_t)row0*NF + 512];
        float2 qf0 = g_qf[(size_t)row0*NF + 512];
        float m0 = kx0.x + sf.x*qf0.x;
        float2 kx1 = g_kx[(size_t)row1*NF + 512];
        float2 qf1 = g_qf[(size_t)row1*NF + 512];
        float m1 = kx1.x + sf.x*qf1.x;
        bufA[F(512)] = make_float2(m0, -m1);
    }
    __syncthreads();
    fft1024_r4(bufA, bufB, tw, t);

    const float invN = 1.0f / 1024.0f;
    #pragma unroll
    for (int r = 0; r < 2; r++) {
        const int row = row0 + r;
        const __half* xr = g_xh + (size_t)row * DIMS;
        float y[4];
        float2 s12 = make_float2(0.f, 0.f);
        #pragma unroll
        for (int i = 0; i < 4; i++) {
            int e = t + 256 * i;
            float2 w = bufB[F(e)];
            float mixv = (r == 0 ? w.x : -w.y) * invN;
            y[i] = __half2float(xr[e]) + mixv;
            s12.x += y[i];
            s12.y += y[i] * y[i];
        }
        s12 = block_sum2<8>(s12, red2);
        float m = s12.x * invN, v = s12.y * invN - m*m;
        float rr = rsqrtf(v + 1e-5f);
        __half* oh = g_x1h + (size_t)row * DIMS;
        #pragma unroll
        for (int i = 0; i < 4; i++) {
            int e = t + 256 * i;
            float ov = (y[i] - m) * rr * g0[e] + beta0[e];
            oh[e] = __float2half_rn(ov);
        }
    }
}

// ---------------- out = LN(x1 + ff)  (fp16 in, fused paired reduction) ----------------
__global__ void __launch_bounds__(512) resid_ln_kernel(
    const float* __restrict__ g1v, const float* __restrict__ beta1,
    float* __restrict__ out)
{
    const int row = blockIdx.x;
    const int t = threadIdx.x;
    __shared__ float2 red2[16];
    const __half2* a = (const __half2*)(g_x1h + (size_t)row * DIMS);
    const __half2* f = (const __half2*)(g_ffh + (size_t)row * DIMS);
    float2 av = __half22float2(a[t]);
    float2 fv = __half22float2(f[t]);
    float y0 = av.x + fv.x;
    float y1 = av.y + fv.y;
    const float invN = 1.0f / 1024.0f;
    float2 s12 = block_sum2<16>(make_float2(y0 + y1, y0*y0 + y1*y1), red2);
    float m = s12.x * invN, v = s12.y * invN - m*m;
    float r = rsqrtf(v + 1e-5f);
    float* o = out + (size_t)row * DIMS;
    o[2*t]   = (y0 - m) * r * g1v[2*t]   + beta1[2*t];
    o[2*t+1] = (y1 - m) * r * g1v[2*t+1] + beta1[2*t+1];
}

// ---------------- launch ----------------
extern "C" void kernel_launch(void* const* d_in, const int* in_sizes, int n_in,
                              void* d_out, int out_size)
{
    const float* x     = (const float*)d_in[0];
    const float* Wq    = (const float*)d_in[1];
    const float* bq    = (const float*)d_in[2];
    const float* gq    = (const float*)d_in[3];
    const float* betaq = (const float*)d_in[4];
    const float* Wk    = (const float*)d_in[5];
    const float* bk    = (const float*)d_in[6];
    const float* gk    = (const float*)d_in[7];
    const float* betak = (const float*)d_in[8];
    const float* g0    = (const float*)d_in[9];
    const float* beta0 = (const float*)d_in[10];
    const float* W1    = (const float*)d_in[11];
    const float* b1    = (const float*)d_in[12];
    const float* W2    = (const float*)d_in[13];
    const float* b2    = (const float*)d_in[14];
    const float* g1    = (const float*)d_in[15];
    const float* beta1 = (const float*)d_in[16];
    float* out = (float*)d_out;

    float *pbr;
    __half *pqkh, *px1h, *ph, *pxh, *pwh, *pffh;
    cudaGetSymbolAddress((void**)&pqkh, g_qkh);
    cudaGetSymbolAddress((void**)&px1h, g_x1h);
    cudaGetSymbolAddress((void**)&ph,   g_h);
    cudaGetSymbolAddress((void**)&pffh, g_ffh);
    cudaGetSymbolAddress((void**)&pxh,  g_xh);
    cudaGetSymbolAddress((void**)&pwh,  g_wh);
    cudaGetSymbolAddress((void**)&pbr,  g_br);

    const int SMEM = NSTAGE * STAGE_BYTES;  // 221184 B
    cudaFuncSetAttribute(gemm_h<0,__half>, cudaFuncAttributeMaxDynamicSharedMemorySize, SMEM);
    cudaFuncSetAttribute(gemm_h<1,__half>, cudaFuncAttributeMaxDynamicSharedMemorySize, SMEM);

    // fork: aux stream converts W1/W2 concurrently with G1
    cudaStream_t s1;
    cudaStreamCreate(&s1);
    cudaEvent_t eFork, eW;
    cudaEventCreateWithFlags(&eFork, cudaEventDisableTiming);
    cudaEventCreateWithFlags(&eW,    cudaEventDisableTiming);

    cudaEventRecord(eFork, 0);
    cudaStreamWaitEvent(s1, eFork, 0);
    conv_w_kernel<<<CONVW_BLOCKS, 256, 0, s1>>>(W1, W2, pwh);
    cudaEventRecord(eW, s1);

    // main: x/Wq/Wk conversion + bias pack
    conv_main_kernel<<<CONVM_BLOCKS, 256>>>(x, Wq, Wk, bq, bk, pxh, pwh);

    // [q|k] = x @ [Wq|Wk]^T + [bq|bk]
    gemm_h<0,__half><<<dim3(2*DIMS/128, ROWS/256), 256, SMEM>>>(pxh, pwh + WQK_OFF, pbr, pqkh, 2*DIMS, DIMS);
    // LN(q), LN(k), forward FFTs (low-register, F swizzle)
    fft_fwd_kernel<<<ROWS/2, 256>>>(gq, betaq, gk, betak);
    // S = sum_s Kx (two-stage)
    reduce_s1_kernel<<<dim3(BATCH, 9, SCHUNK), 256>>>();
    reduce_s2_kernel<<<dim3(BATCH, 9), 64>>>();
    // mix = irfft x2 rows; x1 = LN(x + mix) -> fp16
    fft_inv_ln_kernel<<<ROWS/2, 256>>>(g0, beta0);
    // h = relu(x1 @ W1^T + b1)
    cudaStreamWaitEvent(0, eW, 0);
    gemm_h<1,__half><<<dim3(FFD/128, ROWS/256), 256, SMEM>>>(px1h, pwh + W1_OFF, b1, ph, FFD, DIMS);
    // ff = h @ W2^T + b2 -> fp16
    gemm_h<0,__half><<<dim3(DIMS/128, ROWS/256), 256, SMEM>>>(ph, pwh + W2_OFF, b2, pffh, DIMS, FFD);
    // out = LN(x1 + ff)
    resid_ln_kernel<<<ROWS, 512>>>(g1, beta1, out);
}

// round 16
// speedup vs baseline: 1.0429x; 1.0174x over previous
#include <cuda_runtime.h>
#include <cuda_fp16.h>
#include <math.h>
#include <stdint.h>

#define DIMS 1024
#define FFD  4096
#define BATCH 4
#define SEQ  4096
#define ROWS (BATCH*SEQ)   // 16384
#define NF   513           // rfft bins for N=1024
#define SCHUNK 32

// ---------------- scratch (device globals; no allocation allowed) ----------------
__device__ __half g_qkh[(size_t)ROWS*2*DIMS];
__device__ __half g_x1h[(size_t)ROWS*DIMS];
__device__ __half g_ffh[(size_t)ROWS*DIMS];
__device__ __half g_h  [(size_t)ROWS*FFD];
__device__ __half g_xh [(size_t)ROWS*DIMS];
__device__ __half g_wh [(size_t)(2*DIMS*DIMS + 2*DIMS*FFD)];
__device__ float  g_br [2*DIMS];
__device__ float2 g_kx[(size_t)ROWS*NF];
__device__ float2 g_qf[(size_t)ROWS*NF];
__device__ float2 g_sf[BATCH*NF];
__device__ float2 g_sp[SCHUNK*BATCH*NF];

#define WQK_OFF 0
#define W1_OFF  (2*DIMS*DIMS)
#define W2_OFF  (2*DIMS*DIMS + DIMS*FFD)

// ---------------- PTX helpers ----------------
__device__ __forceinline__ uint32_t smem_u32(const void* p) {
    uint32_t a;
    asm("{ .reg .u64 t; cvta.to.shared.u64 t, %1; cvt.u32.u64 %0, t; }" : "=r"(a) : "l"(p));
    return a;
}
__device__ __forceinline__ uint32_t h2_as_u32(__half2 h) {
    union { __half2 h; uint32_t u; } cvt;
    cvt.h = h;
    return cvt.u;
}
__device__ __forceinline__ void cp16(uint32_t dst, const void* src) {
    asm volatile("cp.async.cg.shared.global [%0], [%1], 16;" :: "r"(dst), "l"(src));
}
#define CP_COMMIT() asm volatile("cp.async.commit_group;" ::: "memory")
template<int N> __device__ __forceinline__ void cp_wait() {
    asm volatile("cp.async.wait_group %0;" :: "n"(N) : "memory");
}
__device__ __forceinline__ void mma_f16(float& c0, float& c1, float& c2, float& c3,
                                        uint32_t a0, uint32_t a1, uint32_t a2, uint32_t a3,
                                        uint32_t b0, uint32_t b1) {
    asm volatile(
        "mma.sync.aligned.m16n8k16.row.col.f32.f16.f16.f32 "
        "{%0,%1,%2,%3}, {%4,%5,%6,%7}, {%8,%9}, {%0,%1,%2,%3};"
        : "+f"(c0), "+f"(c1), "+f"(c2), "+f"(c3)
        : "r"(a0), "r"(a1), "r"(a2), "r"(a3), "r"(b0), "r"(b1));
}
__device__ __forceinline__ void ldsm_x4(uint32_t& r0, uint32_t& r1, uint32_t& r2, uint32_t& r3,
                                        uint32_t addr) {
    asm volatile("ldmatrix.sync.aligned.m8n8.x4.shared.b16 {%0,%1,%2,%3}, [%4];"
                 : "=r"(r0), "=r"(r1), "=r"(r2), "=r"(r3) : "r"(addr));
}

// ---------------- conversion kernels ----------------
__device__ __forceinline__ void conv8(const float* __restrict__ src,
                                      __half* __restrict__ dst, int i) {
    float4 a = ((const float4*)src)[2*i];
    float4 b = ((const float4*)src)[2*i+1];
    uint4 o;
    o.x = h2_as_u32(__floats2half2_rn(a.x, a.y));
    o.y = h2_as_u32(__floats2half2_rn(a.z, a.w));
    o.z = h2_as_u32(__floats2half2_rn(b.x, b.y));
    o.w = h2_as_u32(__floats2half2_rn(b.z, b.w));
    ((uint4*)dst)[i] = o;
}

#define XB   8192
#define WQB  512
#define WKB  512
#define BBLK 8
#define CONVM_BLOCKS (XB + WQB + WKB + BBLK)
__global__ void __launch_bounds__(256) conv_main_kernel(
    const float* __restrict__ x,
    const float* __restrict__ Wq, const float* __restrict__ Wk,
    const float* __restrict__ bq, const float* __restrict__ bk,
    __half* __restrict__ xh, __half* __restrict__ wh)
{
    int bid = blockIdx.x;
    if (bid < XB)            { conv8(x,  xh,                       bid * 256 + threadIdx.x); }
    else if (bid < XB+WQB)   { conv8(Wq, wh + WQK_OFF,             (bid - XB) * 256 + threadIdx.x); }
    else if (bid < XB+WQB+WKB) { conv8(Wk, wh + WQK_OFF + DIMS*DIMS, (bid - XB - WQB) * 256 + threadIdx.x); }
    else {
        int i = (bid - (XB+WQB+WKB)) * 256 + threadIdx.x;
        if (i < DIMS) g_br[i] = bq[i];
        else          g_br[i] = bk[i - DIMS];
    }
}
#define W1B  2048
#define W2B  2048
#define CONVW_BLOCKS (W1B + W2B)
__global__ void __launch_bounds__(256) conv_w_kernel(
    const float* __restrict__ W1, const float* __restrict__ W2,
    __half* __restrict__ wh)
{
    int bid = blockIdx.x;
    if (bid < W1B) conv8(W1, wh + W1_OFF, bid * 256 + threadIdx.x);
    else           conv8(W2, wh + W2_OFF, (bid - W1B) * 256 + threadIdx.x);
}

// ======================= mma.sync fp16 GEMM =======================
#define BK 64
#define ROWB 144
#define A_TILE_BYTES (256*ROWB)
#define B_TILE_BYTES (128*ROWB)
#define STAGE_BYTES (A_TILE_BYTES + B_TILE_BYTES)
#define NSTAGE 4

template<int RELU, typename CT>
__global__ void __launch_bounds__(256, 1)
gemm_h(const __half* __restrict__ A, const __half* __restrict__ B,
       const float* __restrict__ bias, CT* __restrict__ C,
       int N, int K)
{
    extern __shared__ char smem[];
    const int tid = threadIdx.x;
    const int warp = tid >> 5;
    const int lane = tid & 31;
    const int wm = warp >> 1;
    const int wn = warp & 1;
    const int lr = lane >> 2;
    const int lc = lane & 3;

    const __half* Ab = A + (size_t)blockIdx.y * 256 * K;
    const __half* Bb = B + (size_t)blockIdx.x * 128 * K;

    const uint32_t sbase = smem_u32(smem);
    const int ktiles = K / BK;

    uint32_t aoff[4];
    {
        const int l7 = lane & 7;
        const int rsel = (lane >> 3) & 1;
        const int csel = lane >> 4;
        #pragma unroll
        for (int mt = 0; mt < 4; mt++) {
            int r = wm * 64 + mt * 16 + l7 + rsel * 8;
            aoff[mt] = (uint32_t)(r * ROWB + csel * 16);
        }
    }
    uint32_t boff[4];
    {
        const int l7 = lane & 7;
        const int csel = (lane >> 3) & 1;
        const int rsel = lane >> 4;
        #pragma unroll
        for (int pr = 0; pr < 4; pr++) {
            int r = wn * 64 + pr * 16 + rsel * 8 + l7;
            boff[pr] = (uint32_t)(r * ROWB + csel * 16);
        }
    }

    auto load_stage = [&](int stage, int kt) {
        const int k0 = kt * BK;
        const uint32_t sA = sbase + stage * STAGE_BYTES;
        const uint32_t sB = sA + A_TILE_BYTES;
        #pragma unroll
        for (int i = 0; i < 8; i++) {
            int g = i * 256 + tid;
            int r = g >> 3, c = g & 7;
            cp16(sA + r * ROWB + c * 16, Ab + (size_t)r * K + k0 + c * 8);
        }
        #pragma unroll
        for (int i = 0; i < 4; i++) {
            int g = i * 256 + tid;
            int r = g >> 3, c = g & 7;
            cp16(sB + r * ROWB + c * 16, Bb + (size_t)r * K + k0 + c * 8);
        }
    };

    load_stage(0, 0); CP_COMMIT();
    load_stage(1, 1); CP_COMMIT();
    load_stage(2, 2); CP_COMMIT();

    float acc[4][8][4];
    #pragma unroll
    for (int i = 0; i < 4; i++)
        #pragma unroll
        for (int j = 0; j < 8; j++)
            #pragma unroll
            for (int r = 0; r < 4; r++) acc[i][j][r] = 0.f;

    for (int it = 0; it < ktiles; it++) {
        cp_wait<NSTAGE - 2>();
        __syncthreads();

        const uint32_t sA = sbase + (it % NSTAGE) * STAGE_BYTES;
        const uint32_t sB = sA + A_TILE_BYTES;

        const int nt3 = it + NSTAGE - 1;
        if (nt3 < ktiles) load_stage(nt3 % NSTAGE, nt3);
        CP_COMMIT();

        #pragma unroll
        for (int ks = 0; ks < 4; ks++) {
            const uint32_t kb = ks * 32;
            uint32_t a[4][4], b[8][2];
            #pragma unroll
            for (int mt = 0; mt < 4; mt++)
                ldsm_x4(a[mt][0], a[mt][1], a[mt][2], a[mt][3], sA + aoff[mt] + kb);
            #pragma unroll
            for (int pr = 0; pr < 4; pr++)
                ldsm_x4(b[2*pr][0], b[2*pr][1], b[2*pr+1][0], b[2*pr+1][1],
                        sB + boff[pr] + kb);
            #pragma unroll
            for (int mt = 0; mt < 4; mt++)
                #pragma unroll
                for (int nt = 0; nt < 8; nt++)
                    mma_f16(acc[mt][nt][0], acc[mt][nt][1],
                            acc[mt][nt][2], acc[mt][nt][3],
                            a[mt][0], a[mt][1], a[mt][2], a[mt][3],
                            b[nt][0], b[nt][1]);
        }
    }

    const int crow0 = blockIdx.y * 256 + wm * 64;
    const int ccol0 = blockIdx.x * 128 + wn * 64;
    float bb0[8], bb1[8];
    #pragma unroll
    for (int nt = 0; nt < 8; nt++) {
        bb0[nt] = __ldg(bias + ccol0 + nt * 8 + lc * 2);
        bb1[nt] = __ldg(bias + ccol0 + nt * 8 + lc * 2 + 1);
    }
    #pragma unroll
    for (int mt = 0; mt < 4; mt++) {
        #pragma unroll
        for (int nt = 0; nt < 8; nt++) {
            const int r0 = crow0 + mt * 16 + lr;
            const int c0 = ccol0 + nt * 8 + lc * 2;
            float v0 = acc[mt][nt][0] + bb0[nt];
            float v1 = acc[mt][nt][1] + bb1[nt];
            float v2 = acc[mt][nt][2] + bb0[nt];
            float v3 = acc[mt][nt][3] + bb1[nt];
            if (RELU) {
                v0 = fmaxf(v0, 0.f); v1 = fmaxf(v1, 0.f);
                v2 = fmaxf(v2, 0.f); v3 = fmaxf(v3, 0.f);
            }
            if (sizeof(CT) == 2) {
                *(__half2*)((__half*)C + (size_t)r0 * N + c0)       = __floats2half2_rn(v0, v1);
                *(__half2*)((__half*)C + (size_t)(r0 + 8) * N + c0) = __floats2half2_rn(v2, v3);
            } else {
                *(float2*)((float*)C + (size_t)r0 * N + c0)       = make_float2(v0, v1);
                *(float2*)((float*)C + (size_t)(r0 + 8) * N + c0) = make_float2(v2, v3);
            }
        }
    }
}

// ---------------- FFT path helpers ----------------
__device__ __forceinline__ float2 cmulf(float2 a, float2 b) {
    return make_float2(a.x*b.x - a.y*b.y, a.x*b.y + a.y*b.x);
}
#define F(i) ((i) ^ ((((i) >> 5) & 7) << 2))

template<int NW>
__device__ __forceinline__ float2 block_sum2(float2 v, volatile float2* red) {
    int t = threadIdx.x;
    #pragma unroll
    for (int o = 16; o; o >>= 1) {
        v.x += __shfl_xor_sync(0xffffffffu, v.x, o);
        v.y += __shfl_xor_sync(0xffffffffu, v.y, o);
    }
    if ((t & 31) == 0) { red[t >> 5].x = v.x; red[t >> 5].y = v.y; }
    __syncthreads();
    if (t == 0) {
        float2 s = make_float2(0.f, 0.f);
        #pragma unroll
        for (int i = 0; i < NW; i++) { s.x += red[i].x; s.y += red[i].y; }
        red[0].x = s.x; red[0].y = s.y;
    }
    __syncthreads();
    float2 r = make_float2(red[0].x, red[0].y);
    __syncthreads();
    return r;
}

// 1024-pt radix-4 Stockham FFT (forward), 256 threads, 5 stages. Result in bufB.
__device__ __forceinline__ void fft1024_r4(float2* bufA, float2* bufB,
                                           const float2* tw, int v) {
    float2* src = bufA; float2* dst = bufB;
    #pragma unroll
    for (int st = 0; st < 5; st++) {
        const int s = 1 << (2 * st);
        const int idx = v & ~(s - 1);
        float2 w1 = tw[idx];
        float2 w2 = tw[2*idx];
        float2 w3 = tw[3*idx];
        float2 a = src[F(v)];
        float2 b = src[F(v + 256)];
        float2 c = src[F(v + 512)];
        float2 d = src[F(v + 768)];
        float2 apc = make_float2(a.x + c.x, a.y + c.y);
        float2 amc = make_float2(a.x - c.x, a.y - c.y);
        float2 bpd = make_float2(b.x + d.x, b.y + d.y);
        float2 jbmd = make_float2(-(b.y - d.y), b.x - d.x);
        const int bo = v + 3 * idx;
        dst[F(bo)]         = make_float2(apc.x + bpd.x, apc.y + bpd.y);
        dst[F(bo + s)]     = cmulf(w1, make_float2(amc.x - jbmd.x, amc.y - jbmd.y));
        dst[F(bo + 2*s)]   = cmulf(w2, make_float2(apc.x - bpd.x, apc.y - bpd.y));
        dst[F(bo + 3*s)]   = cmulf(w3, make_float2(amc.x + jbmd.x, amc.y + jbmd.y));
        __syncthreads();
        float2* tmp = src; src = dst; dst = tmp;
    }
}

// ---------------- forward: LN(q,k) x2 rows; 3 FFTs per 2 rows (occupancy-forced) ----------------
__global__ void __launch_bounds__(256, 4) fft_fwd_kernel(
    const float* __restrict__ gq, const float* __restrict__ betaq,
    const float* __restrict__ gk, const float* __restrict__ betak)
{
    const int row0 = blockIdx.x * 2;
    const int row1 = row0 + 1;
    const int t = threadIdx.x;
    __shared__ float2 tw[768];
    __shared__ float2 bufA[1024];
    __shared__ float2 bufB[1024];
    __shared__ float2 red2[8];

    #pragma unroll
    for (int j = 0; j < 3; j++) {
        int i = t + 256 * j;
        float s_, c_;
        sincospif((float)i * (1.0f/512.0f), &s_, &c_);
        tw[i] = make_float2(c_, -s_);
    }

    const float invN = 1.0f / 1024.0f;
    float xv[2][4], qn[2][4], kn[2][4];
    #pragma unroll
    for (int r = 0; r < 2; r++) {
        const int row = row0 + r;
        const __half* xr = g_xh  + (size_t)row * DIMS;
        const __half* qr = g_qkh + (size_t)row * 2 * DIMS;
        const __half* kr = qr + DIMS;
        float qv[4], kv[4];
        #pragma unroll
        for (int i = 0; i < 4; i++) {
            int e = t + 256 * i;
            xv[r][i] = __half2float(xr[e]);
            qv[i] = __half2float(qr[e]);
            kv[i] = __half2float(kr[e]);
        }
        float2 s1 = make_float2(0.f, 0.f), s2 = make_float2(0.f, 0.f);
        #pragma unroll
        for (int i = 0; i < 4; i++) {
            s1.x += qv[i]; s1.y += kv[i];
            s2.x += qv[i]*qv[i]; s2.y += kv[i]*kv[i];
        }
        s1 = block_sum2<8>(s1, red2);
        s2 = block_sum2<8>(s2, red2);
        float mq = s1.x * invN, vq = s2.x * invN - mq*mq;
        float rq = rsqrtf(vq + 1e-5f);
        float mk = s1.y * invN, vk = s2.y * invN - mk*mk;
        float rk = rsqrtf(vk + 1e-5f);
        #pragma unroll
        for (int i = 0; i < 4; i++) {
            int e = t + 256 * i;
            qn[r][i] = (qv[i] - mq) * rq * gq[e] + betaq[e];
            kn[r][i] = (kv[i] - mk) * rk * gk[e] + betak[e];
        }
    }

    #pragma unroll
    for (int r = 0; r < 2; r++) {
        const int row = row0 + r;
        #pragma unroll
        for (int i = 0; i < 4; i++) bufA[F(t + 256*i)] = make_float2(xv[r][i], kn[r][i]);
        __syncthreads();
        fft1024_r4(bufA, bufB, tw, t);
        #pragma unroll
        for (int jj = 0; jj < 2; jj++) {
            int j = t + 256 * jj;
            float2 z  = bufB[F(j)];
            float2 zn = bufB[F((1024 - j) & 1023)];
            float2 xf = make_float2(0.5f*(z.x + zn.x), 0.5f*(z.y - zn.y));
            float2 df = make_float2(z.x - zn.x, z.y + zn.y);
            float2 kf = make_float2(0.5f*df.y, -0.5f*df.x);
            g_kx[(size_t)row*NF + j] = cmulf(xf, kf);
        }
        if (t == 0) {
            float2 z5 = bufB[F(512)];
            g_kx[(size_t)row*NF + 512] = make_float2(z5.x * z5.y, 0.f);
        }
        __syncthreads();
    }

    #pragma unroll
    for (int i = 0; i < 4; i++) bufA[F(t + 256*i)] = make_float2(qn[0][i], qn[1][i]);
    __syncthreads();
    fft1024_r4(bufA, bufB, tw, t);
    #pragma unroll
    for (int jj = 0; jj < 2; jj++) {
        int j = t + 256 * jj;
        float2 z  = bufB[F(j)];
        float2 zn = bufB[F((1024 - j) & 1023)];
        float2 q0 = make_float2(0.5f*(z.x + zn.x), 0.5f*(z.y - zn.y));
        float2 df = make_float2(z.x - zn.x, z.y + zn.y);
        float2 q1 = make_float2(0.5f*df.y, -0.5f*df.x);
        g_qf[(size_t)row0*NF + j] = q0;
        g_qf[(size_t)row1*NF + j] = q1;
    }
    if (t == 0) {
        float2 z5 = bufB[F(512)];
        g_qf[(size_t)row0*NF + 512] = make_float2(z5.x, 0.f);
        g_qf[(size_t)row1*NF + 512] = make_float2(z5.y, 0.f);
    }
}

// ---------------- reduce S stage 1 + 2 ----------------
__global__ void __launch_bounds__(256) reduce_s1_kernel() {
    const int b  = blockIdx.x;
    const int jc = blockIdx.y;
    const int sc = blockIdx.z;
    const int t  = threadIdx.x;
    const int jl = t & 63;
    const int sl = t >> 6;
    const int j  = jc * 64 + jl;
    float2 acc = make_float2(0.f, 0.f);
    if (j < NF) {
        const int s0 = sc * 128;
        const float2* p = g_kx + (size_t)b * SEQ * NF + (size_t)s0 * NF + j;
        for (int s = sl; s < 128; s += 4) {
            float2 v = p[(size_t)s * NF];
            acc.x += v.x; acc.y += v.y;
        }
    }
    __shared__ float2 red[256];
    red[t] = acc;
    __syncthreads();
    if (t < 128) { red[t].x += red[t+128].x; red[t].y += red[t+128].y; }
    __syncthreads();
    if (t < 64) {
        red[t].x += red[t+64].x; red[t].y += red[t+64].y;
        if (j < NF) g_sp[((size_t)sc * BATCH + b) * NF + j] = red[t];
    }
}
__global__ void __launch_bounds__(64) reduce_s2_kernel() {
    const int b  = blockIdx.x;
    const int jc = blockIdx.y;
    const int j  = jc * 64 + threadIdx.x;
    if (j >= NF) return;
    float2 acc = make_float2(0.f, 0.f);
    #pragma unroll
    for (int sc = 0; sc < SCHUNK; sc++) {
        float2 v = g_sp[((size_t)sc * BATCH + b) * NF + j];
        acc.x += v.x; acc.y += v.y;
    }
    g_sf[b * NF + j] = acc;
}

// ---------------- inverse: 1 FFT per 2 rows; LN(x+mix) x2 -> fp16 x1 ----------------
__global__ void __launch_bounds__(256, 4) fft_inv_ln_kernel(
    const float* __restrict__ g0, const float* __restrict__ beta0)
{
    const int row0 = blockIdx.x * 2;
    const int row1 = row0 + 1;
    const int b = row0 >> 12;
    const int t = threadIdx.x;
    __shared__ float2 tw[768];
    __shared__ float2 bufA[1024];
    __shared__ float2 bufB[1024];
    __shared__ float2 red2[8];

    #pragma unroll
    for (int j = 0; j < 3; j++) {
        int i = t + 256 * j;
        float s_, c_;
        sincospif((float)i * (1.0f/512.0f), &s_, &c_);
        tw[i] = make_float2(c_, -s_);
    }

    #pragma unroll
    for (int jj = 0; jj < 2; jj++) {
        int j = t + 256 * jj;
        float2 sf = g_sf[b*NF + j];
        float2 kx0 = g_kx[(size_t)row0*NF + j];
        float2 qf0 = g_qf[(size_t)row0*NF + j];
        float2 m0 = make_float2(kx0.x + sf.x*qf0.x + sf.y*qf0.y,
                                kx0.y - sf.x*qf0.y + sf.y*qf0.x);
        float2 kx1 = g_kx[(size_t)row1*NF + j];
        float2 qf1 = g_qf[(size_t)row1*NF + j];
        float2 m1 = make_float2(kx1.x + sf.x*qf1.x + sf.y*qf1.y,
                                kx1.y - sf.x*qf1.y + sf.y*qf1.x);
        bufA[F(j)] = make_float2(m0.x - m1.y, -m0.y - m1.x);
        if (j > 0) bufA[F(1024 - j)] = make_float2(m0.x + m1.y, m0.y - m1.x);
    }
    if (t == 0) {
        float2 sf = g_sf[b*NF + 512];
        float2 kx0 = g_kx[(size_t)row0*NF + 512];
        float2 qf0 = g_qf[(size_t)row0*NF + 512];
        float m0 = kx0.x + sf.x*qf0.x;
        float2 kx1 = g_kx[(size_t)row1*NF + 512];
        float2 qf1 = g_qf[(size_t)row1*NF + 512];
        float m1 = kx1.x + sf.x*qf1.x;
        bufA[F(512)] = make_float2(m0, -m1);
    }
    __syncthreads();
    fft1024_r4(bufA, bufB, tw, t);

    const float invN = 1.0f / 1024.0f;
    #pragma unroll
    for (int r = 0; r < 2; r++) {
        const int row = row0 + r;
        const __half* xr = g_xh + (size_t)row * DIMS;
        float y[4];
        float2 s12 = make_float2(0.f, 0.f);
        #pragma unroll
        for (int i = 0; i < 4; i++) {
            int e = t + 256 * i;
            float2 w = bufB[F(e)];
            float mixv = (r == 0 ? w.x : -w.y) * invN;
            y[i] = __half2float(xr[e]) + mixv;
            s12.x += y[i];
            s12.y += y[i] * y[i];
        }
        s12 = block_sum2<8>(s12, red2);
        float m = s12.x * invN, v = s12.y * invN - m*m;
        float rr = rsqrtf(v + 1e-5f);
        __half* oh = g_x1h + (size_t)row * DIMS;
        #pragma unroll
        for (int i = 0; i < 4; i++) {
            int e = t + 256 * i;
            float ov = (y[i] - m) * rr * g0[e] + beta0[e];
            oh[e] = __float2half_rn(ov);
        }
    }
}

// ---------------- out = LN(x1 + ff)  (fp16 in, fused paired reduction) ----------------
__global__ void __launch_bounds__(512) resid_ln_kernel(
    const float* __restrict__ g1v, const float* __restrict__ beta1,
    float* __restrict__ out)
{
    const int row = blockIdx.x;
    const int t = threadIdx.x;
    __shared__ float2 red2[16];
    const __half2* a = (const __half2*)(g_x1h + (size_t)row * DIMS);
    const __half2* f = (const __half2*)(g_ffh + (size_t)row * DIMS);
    float2 av = __half22float2(a[t]);
    float2 fv = __half22float2(f[t]);
    float y0 = av.x + fv.x;
    float y1 = av.y + fv.y;
    const float invN = 1.0f / 1024.0f;
    float2 s12 = block_sum2<16>(make_float2(y0 + y1, y0*y0 + y1*y1), red2);
    float m = s12.x * invN, v = s12.y * invN - m*m;
    float r = rsqrtf(v + 1e-5f);
    float* o = out + (size_t)row * DIMS;
    o[2*t]   = (y0 - m) * r * g1v[2*t]   + beta1[2*t];
    o[2*t+1] = (y1 - m) * r * g1v[2*t+1] + beta1[2*t+1];
}

// ---------------- launch ----------------
extern "C" void kernel_launch(void* const* d_in, const int* in_sizes, int n_in,
                              void* d_out, int out_size)
{
    const float* x     = (const float*)d_in[0];
    const float* Wq    = (const float*)d_in[1];
    const float* bq    = (const float*)d_in[2];
    const float* gq    = (const float*)d_in[3];
    const float* betaq = (const float*)d_in[4];
    const float* Wk    = (const float*)d_in[5];
    const float* bk    = (const float*)d_in[6];
    const float* gk    = (const float*)d_in[7];
    const float* betak = (const float*)d_in[8];
    const float* g0    = (const float*)d_in[9];
    const float* beta0 = (const float*)d_in[10];
    const float* W1    = (const float*)d_in[11];
    const float* b1    = (const float*)d_in[12];
    const float* W2    = (const float*)d_in[13];
    const float* b2    = (const float*)d_in[14];
    const float* g1    = (const float*)d_in[15];
    const float* beta1 = (const float*)d_in[16];
    float* out = (float*)d_out;

    float *pbr;
    __half *pqkh, *px1h, *ph, *pxh, *pwh, *pffh;
    cudaGetSymbolAddress((void**)&pqkh, g_qkh);
    cudaGetSymbolAddress((void**)&px1h, g_x1h);
    cudaGetSymbolAddress((void**)&ph,   g_h);
    cudaGetSymbolAddress((void**)&pffh, g_ffh);
    cudaGetSymbolAddress((void**)&pxh,  g_xh);
    cudaGetSymbolAddress((void**)&pwh,  g_wh);
    cudaGetSymbolAddress((void**)&pbr,  g_br);

    const int SMEM = NSTAGE * STAGE_BYTES;  // 221184 B
    cudaFuncSetAttribute(gemm_h<0,__half>, cudaFuncAttributeMaxDynamicSharedMemorySize, SMEM);
    cudaFuncSetAttribute(gemm_h<1,__half>, cudaFuncAttributeMaxDynamicSharedMemorySize, SMEM);

    // fork: aux stream converts W1/W2 concurrently with G1
    cudaStream_t s1;
    cudaStreamCreate(&s1);
    cudaEvent_t eFork, eW;
    cudaEventCreateWithFlags(&eFork, cudaEventDisableTiming);
    cudaEventCreateWithFlags(&eW,    cudaEventDisableTiming);

    cudaEventRecord(eFork, 0);
    cudaStreamWaitEvent(s1, eFork, 0);
    conv_w_kernel<<<CONVW_BLOCKS, 256, 0, s1>>>(W1, W2, pwh);
    cudaEventRecord(eW, s1);

    // main: x/Wq/Wk conversion + bias pack
    conv_main_kernel<<<CONVM_BLOCKS, 256>>>(x, Wq, Wk, bq, bk, pxh, pwh);

    // [q|k] = x @ [Wq|Wk]^T + [bq|bk]
    gemm_h<0,__half><<<dim3(2*DIMS/128, ROWS/256), 256, SMEM>>>(pxh, pwh + WQK_OFF, pbr, pqkh, 2*DIMS, DIMS);
    // LN(q), LN(k), forward FFTs (round-13 body, occupancy forced to 4)
    fft_fwd_kernel<<<ROWS/2, 256>>>(gq, betaq, gk, betak);
    // S = sum_s Kx (two-stage)
    reduce_s1_kernel<<<dim3(BATCH, 9, SCHUNK), 256>>>();
    reduce_s2_kernel<<<dim3(BATCH, 9), 64>>>();
    // mix = irfft x2 rows; x1 = LN(x + mix) -> fp16
    fft_inv_ln_kernel<<<ROWS/2, 256>>>(g0, beta0);
    // h = relu(x1 @ W1^T + b1)
    cudaStreamWaitEvent(0, eW, 0);
    gemm_h<1,__half><<<dim3(FFD/128, ROWS/256), 256, SMEM>>>(px1h, pwh + W1_OFF, b1, ph, FFD, DIMS);
    // ff = h @ W2^T + b2 -> fp16
    gemm_h<0,__half><<<dim3(DIMS/128, ROWS/256), 256, SMEM>>>(ph, pwh + W2_OFF, b2, pffh, DIMS, FFD);
    // out = LN(x1 + ff)
    resid_ln_kernel<<<ROWS, 512>>>(g1, beta1, out);
}

// round 17
// speedup vs baseline: 1.0504x; 1.0072x over previous
#include <cuda_runtime.h>
#include <cuda_fp16.h>
#include <math.h>
#include <stdint.h>

#define DIMS 1024
#define FFD  4096
#define BATCH 4
#define SEQ  4096
#define ROWS (BATCH*SEQ)   // 16384
#define NF   513           // rfft bins for N=1024
#define SCHUNK 32

// ---------------- scratch (device globals; no allocation allowed) ----------------
__device__ __half g_qkh[(size_t)ROWS*2*DIMS];
__device__ __half g_x1h[(size_t)ROWS*DIMS];
__device__ __half g_ffh[(size_t)ROWS*DIMS];
__device__ __half g_h  [(size_t)ROWS*FFD];
__device__ __half g_xh [(size_t)ROWS*DIMS];
__device__ __half g_wh [(size_t)(2*DIMS*DIMS + 2*DIMS*FFD)];
__device__ float  g_br [2*DIMS];
__device__ float2 g_kx[(size_t)ROWS*NF];
__device__ float2 g_qf[(size_t)ROWS*NF];
__device__ float2 g_sf[BATCH*NF];
__device__ float2 g_sp[SCHUNK*BATCH*NF];

#define WQK_OFF 0
#define W1_OFF  (2*DIMS*DIMS)
#define W2_OFF  (2*DIMS*DIMS + DIMS*FFD)

// ---------------- PTX helpers ----------------
__device__ __forceinline__ uint32_t smem_u32(const void* p) {
    uint32_t a;
    asm("{ .reg .u64 t; cvta.to.shared.u64 t, %1; cvt.u32.u64 %0, t; }" : "=r"(a) : "l"(p));
    return a;
}
__device__ __forceinline__ uint32_t h2_as_u32(__half2 h) {
    union { __half2 h; uint32_t u; } cvt;
    cvt.h = h;
    return cvt.u;
}
__device__ __forceinline__ void cp16(uint32_t dst, const void* src) {
    asm volatile("cp.async.cg.shared.global [%0], [%1], 16;" :: "r"(dst), "l"(src));
}
#define CP_COMMIT() asm volatile("cp.async.commit_group;" ::: "memory")
template<int N> __device__ __forceinline__ void cp_wait() {
    asm volatile("cp.async.wait_group %0;" :: "n"(N) : "memory");
}
__device__ __forceinline__ void mma_f16(float& c0, float& c1, float& c2, float& c3,
                                        uint32_t a0, uint32_t a1, uint32_t a2, uint32_t a3,
                                        uint32_t b0, uint32_t b1) {
    asm volatile(
        "mma.sync.aligned.m16n8k16.row.col.f32.f16.f16.f32 "
        "{%0,%1,%2,%3}, {%4,%5,%6,%7}, {%8,%9}, {%0,%1,%2,%3};"
        : "+f"(c0), "+f"(c1), "+f"(c2), "+f"(c3)
        : "r"(a0), "r"(a1), "r"(a2), "r"(a3), "r"(b0), "r"(b1));
}
__device__ __forceinline__ void ldsm_x4(uint32_t& r0, uint32_t& r1, uint32_t& r2, uint32_t& r3,
                                        uint32_t addr) {
    asm volatile("ldmatrix.sync.aligned.m8n8.x4.shared.b16 {%0,%1,%2,%3}, [%4];"
                 : "=r"(r0), "=r"(r1), "=r"(r2), "=r"(r3) : "r"(addr));
}

// ---------------- conversion kernels ----------------
__device__ __forceinline__ void conv8(const float* __restrict__ src,
                                      __half* __restrict__ dst, int i) {
    float4 a = ((const float4*)src)[2*i];
    float4 b = ((const float4*)src)[2*i+1];
    uint4 o;
    o.x = h2_as_u32(__floats2half2_rn(a.x, a.y));
    o.y = h2_as_u32(__floats2half2_rn(a.z, a.w));
    o.z = h2_as_u32(__floats2half2_rn(b.x, b.y));
    o.w = h2_as_u32(__floats2half2_rn(b.z, b.w));
    ((uint4*)dst)[i] = o;
}

#define XB   8192
#define WQB  512
#define WKB  512
#define BBLK 8
#define CONVM_BLOCKS (XB + WQB + WKB + BBLK)
__global__ void __launch_bounds__(256) conv_main_kernel(
    const float* __restrict__ x,
    const float* __restrict__ Wq, const float* __restrict__ Wk,
    const float* __restrict__ bq, const float* __restrict__ bk,
    __half* __restrict__ xh, __half* __restrict__ wh)
{
    int bid = blockIdx.x;
    if (bid < XB)            { conv8(x,  xh,                       bid * 256 + threadIdx.x); }
    else if (bid < XB+WQB)   { conv8(Wq, wh + WQK_OFF,             (bid - XB) * 256 + threadIdx.x); }
    else if (bid < XB+WQB+WKB) { conv8(Wk, wh + WQK_OFF + DIMS*DIMS, (bid - XB - WQB) * 256 + threadIdx.x); }
    else {
        int i = (bid - (XB+WQB+WKB)) * 256 + threadIdx.x;
        if (i < DIMS) g_br[i] = bq[i];
        else          g_br[i] = bk[i - DIMS];
    }
}
#define W1B  2048
#define W2B  2048
#define CONVW_BLOCKS (W1B + W2B)
__global__ void __launch_bounds__(256) conv_w_kernel(
    const float* __restrict__ W1, const float* __restrict__ W2,
    __half* __restrict__ wh)
{
    int bid = blockIdx.x;
    if (bid < W1B) conv8(W1, wh + W1_OFF, bid * 256 + threadIdx.x);
    else           conv8(W2, wh + W2_OFF, (bid - W1B) * 256 + threadIdx.x);
}

// ======================= mma.sync fp16 GEMM =======================
#define BK 64
#define ROWB 144
#define A_TILE_BYTES (256*ROWB)
#define B_TILE_BYTES (128*ROWB)
#define STAGE_BYTES (A_TILE_BYTES + B_TILE_BYTES)
#define NSTAGE 4

template<int RELU, typename CT>
__global__ void __launch_bounds__(256, 1)
gemm_h(const __half* __restrict__ A, const __half* __restrict__ B,
       const float* __restrict__ bias, CT* __restrict__ C,
       int N, int K)
{
    extern __shared__ char smem[];
    const int tid = threadIdx.x;
    const int warp = tid >> 5;
    const int lane = tid & 31;
    const int wm = warp >> 1;
    const int wn = warp & 1;
    const int lr = lane >> 2;
    const int lc = lane & 3;

    const __half* Ab = A + (size_t)blockIdx.y * 256 * K;
    const __half* Bb = B + (size_t)blockIdx.x * 128 * K;

    const uint32_t sbase = smem_u32(smem);
    const int ktiles = K / BK;

    uint32_t aoff[4];
    {
        const int l7 = lane & 7;
        const int rsel = (lane >> 3) & 1;
        const int csel = lane >> 4;
        #pragma unroll
        for (int mt = 0; mt < 4; mt++) {
            int r = wm * 64 + mt * 16 + l7 + rsel * 8;
            aoff[mt] = (uint32_t)(r * ROWB + csel * 16);
        }
    }
    uint32_t boff[4];
    {
        const int l7 = lane & 7;
        const int csel = (lane >> 3) & 1;
        const int rsel = lane >> 4;
        #pragma unroll
        for (int pr = 0; pr < 4; pr++) {
            int r = wn * 64 + pr * 16 + rsel * 8 + l7;
            boff[pr] = (uint32_t)(r * ROWB + csel * 16);
        }
    }

    auto load_stage = [&](int stage, int kt) {
        const int k0 = kt * BK;
        const uint32_t sA = sbase + stage * STAGE_BYTES;
        const uint32_t sB = sA + A_TILE_BYTES;
        #pragma unroll
        for (int i = 0; i < 8; i++) {
            int g = i * 256 + tid;
            int r = g >> 3, c = g & 7;
            cp16(sA + r * ROWB + c * 16, Ab + (size_t)r * K + k0 + c * 8);
        }
        #pragma unroll
        for (int i = 0; i < 4; i++) {
            int g = i * 256 + tid;
            int r = g >> 3, c = g & 7;
            cp16(sB + r * ROWB + c * 16, Bb + (size_t)r * K + k0 + c * 8);
        }
    };

    load_stage(0, 0); CP_COMMIT();
    load_stage(1, 1); CP_COMMIT();
    load_stage(2, 2); CP_COMMIT();

    float acc[4][8][4];
    #pragma unroll
    for (int i = 0; i < 4; i++)
        #pragma unroll
        for (int j = 0; j < 8; j++)
            #pragma unroll
            for (int r = 0; r < 4; r++) acc[i][j][r] = 0.f;

    for (int it = 0; it < ktiles; it++) {
        cp_wait<NSTAGE - 2>();
        __syncthreads();

        const uint32_t sA = sbase + (it % NSTAGE) * STAGE_BYTES;
        const uint32_t sB = sA + A_TILE_BYTES;

        const int nt3 = it + NSTAGE - 1;
        if (nt3 < ktiles) load_stage(nt3 % NSTAGE, nt3);
        CP_COMMIT();

        #pragma unroll
        for (int ks = 0; ks < 4; ks++) {
            const uint32_t kb = ks * 32;
            uint32_t a[4][4], b[8][2];
            #pragma unroll
            for (int mt = 0; mt < 4; mt++)
                ldsm_x4(a[mt][0], a[mt][1], a[mt][2], a[mt][3], sA + aoff[mt] + kb);
            #pragma unroll
            for (int pr = 0; pr < 4; pr++)
                ldsm_x4(b[2*pr][0], b[2*pr][1], b[2*pr+1][0], b[2*pr+1][1],
                        sB + boff[pr] + kb);
            #pragma unroll
            for (int mt = 0; mt < 4; mt++)
                #pragma unroll
                for (int nt = 0; nt < 8; nt++)
                    mma_f16(acc[mt][nt][0], acc[mt][nt][1],
                            acc[mt][nt][2], acc[mt][nt][3],
                            a[mt][0], a[mt][1], a[mt][2], a[mt][3],
                            b[nt][0], b[nt][1]);
        }
    }

    const int crow0 = blockIdx.y * 256 + wm * 64;
    const int ccol0 = blockIdx.x * 128 + wn * 64;
    float bb0[8], bb1[8];
    #pragma unroll
    for (int nt = 0; nt < 8; nt++) {
        bb0[nt] = __ldg(bias + ccol0 + nt * 8 + lc * 2);
        bb1[nt] = __ldg(bias + ccol0 + nt * 8 + lc * 2 + 1);
    }
    #pragma unroll
    for (int mt = 0; mt < 4; mt++) {
        #pragma unroll
        for (int nt = 0; nt < 8; nt++) {
            const int r0 = crow0 + mt * 16 + lr;
            const int c0 = ccol0 + nt * 8 + lc * 2;
            float v0 = acc[mt][nt][0] + bb0[nt];
            float v1 = acc[mt][nt][1] + bb1[nt];
            float v2 = acc[mt][nt][2] + bb0[nt];
            float v3 = acc[mt][nt][3] + bb1[nt];
            if (RELU) {
                v0 = fmaxf(v0, 0.f); v1 = fmaxf(v1, 0.f);
                v2 = fmaxf(v2, 0.f); v3 = fmaxf(v3, 0.f);
            }
            if (sizeof(CT) == 2) {
                *(__half2*)((__half*)C + (size_t)r0 * N + c0)       = __floats2half2_rn(v0, v1);
                *(__half2*)((__half*)C + (size_t)(r0 + 8) * N + c0) = __floats2half2_rn(v2, v3);
            } else {
                *(float2*)((float*)C + (size_t)r0 * N + c0)       = make_float2(v0, v1);
                *(float2*)((float*)C + (size_t)(r0 + 8) * N + c0) = make_float2(v2, v3);
            }
        }
    }
}

// ---------------- FFT path helpers ----------------
__device__ __forceinline__ float2 cmulf(float2 a, float2 b) {
    return make_float2(a.x*b.x - a.y*b.y, a.x*b.y + a.y*b.x);
}
// swizzle for merge01 -> merge23 handoff buffer
#define SW(i) (((i) & ~15) | (((i) ^ ((i) >> 4)) & 15))

template<int NW>
__device__ __forceinline__ float2 block_sum2(float2 v, volatile float2* red) {
    int t = threadIdx.x;
    #pragma unroll
    for (int o = 16; o; o >>= 1) {
        v.x += __shfl_xor_sync(0xffffffffu, v.x, o);
        v.y += __shfl_xor_sync(0xffffffffu, v.y, o);
    }
    if ((t & 31) == 0) { red[t >> 5].x = v.x; red[t >> 5].y = v.y; }
    __syncthreads();
    if (t == 0) {
        float2 s = make_float2(0.f, 0.f);
        #pragma unroll
        for (int i = 0; i < NW; i++) { s.x += red[i].x; s.y += red[i].y; }
        red[0].x = s.x; red[0].y = s.y;
    }
    __syncthreads();
    float2 r = make_float2(red[0].x, red[0].y);
    __syncthreads();
    return r;
}

// radix-4 butterfly (pre-twiddle components)
__device__ __forceinline__ void bf4(float2 a, float2 b, float2 c, float2 d,
                                    float2& o0, float2& o1, float2& o2, float2& o3) {
    float2 apc = make_float2(a.x + c.x, a.y + c.y);
    float2 amc = make_float2(a.x - c.x, a.y - c.y);
    float2 bpd = make_float2(b.x + d.x, b.y + d.y);
    float2 jb  = make_float2(-(b.y - d.y), b.x - d.x);   // i*(b-d)
    o0 = make_float2(apc.x + bpd.x, apc.y + bpd.y);
    o1 = make_float2(amc.x - jb.x,  amc.y - jb.y);
    o2 = make_float2(apc.x - bpd.x, apc.y - bpd.y);
    o3 = make_float2(amc.x + jb.x,  amc.y + jb.y);
}

// 1024-pt radix-4 Stockham FFT, 3 shared phases:
// merged stages (0,1), merged stages (2,3), plain stage 4 (twiddle-free).
// Input bufA (identity), output bufB (identity). Caller syncs after filling bufA.
__device__ __forceinline__ void fft1024_m3(float2* bufA, float2* bufB,
                                           const float2* tw, int t) {
    // phase 1: stages 0+1, 64 threads. bufA(identity) -> bufB(SW)
    if (t < 64) {
        float2 y[4][4];
        #pragma unroll
        for (int n = 0; n < 4; n++) {
            const int p = t + 64 * n;
            float2 o0, o1, o2, o3;
            bf4(bufA[p], bufA[p+256], bufA[p+512], bufA[p+768], o0, o1, o2, o3);
            y[n][0] = o0;
            y[n][1] = cmulf(tw[p],   o1);
            y[n][2] = cmulf(tw[2*p], o2);
            y[n][3] = cmulf(tw[3*p], o3);
        }
        const int idx1 = 4 * t;
        const float2 w1 = tw[idx1], w2 = tw[2*idx1], w3 = tw[3*idx1];
        #pragma unroll
        for (int kh = 0; kh < 4; kh++) {
            float2 o0, o1, o2, o3;
            bf4(y[0][kh], y[1][kh], y[2][kh], y[3][kh], o0, o1, o2, o3);
            const int base = 16 * t + kh;
            bufB[SW(base)]      = o0;
            bufB[SW(base + 4)]  = cmulf(w1, o1);
            bufB[SW(base + 8)]  = cmulf(w2, o2);
            bufB[SW(base + 12)] = cmulf(w3, o3);
        }
    }
    __syncthreads();
    // phase 2: stages 2+3, 64 threads. bufB(SW) -> bufA(identity)
    if (t < 64) {
        const int pp = t >> 4;      // 0..3
        const int q  = t & 15;      // 0..15
        float2 y[4][4];
        #pragma unroll
        for (int n = 0; n < 4; n++) {
            const int P = pp + 4 * n;
            const int v = P * 16 + q;
            float2 o0, o1, o2, o3;
            bf4(bufB[SW(v)], bufB[SW(v+256)], bufB[SW(v+512)], bufB[SW(v+768)],
                o0, o1, o2, o3);
            const int idx = 16 * P;
            y[n][0] = o0;
            y[n][1] = cmulf(tw[idx],   o1);
            y[n][2] = cmulf(tw[2*idx], o2);
            y[n][3] = cmulf(tw[3*idx], o3);
        }
        const int idx3 = 64 * pp;
        const float2 w1 = tw[idx3], w2 = tw[2*idx3], w3 = tw[3*idx3];
        #pragma unroll
        for (int kh = 0; kh < 4; kh++) {
            float2 o0, o1, o2, o3;
            bf4(y[0][kh], y[1][kh], y[2][kh], y[3][kh], o0, o1, o2, o3);
            const int base = 256 * pp + 16 * kh + q;
            bufA[base]       = o0;
            bufA[base + 64]  = cmulf(w1, o1);
            bufA[base + 128] = cmulf(w2, o2);
            bufA[base + 192] = cmulf(w3, o3);
        }
    }
    __syncthreads();
    // phase 3: stage 4 (idx=0, no twiddles), 256 threads. bufA -> bufB (identity)
    {
        float2 o0, o1, o2, o3;
        bf4(bufA[t], bufA[t+256], bufA[t+512], bufA[t+768], o0, o1, o2, o3);
        bufB[t]       = o0;
        bufB[t + 256] = o1;
        bufB[t + 512] = o2;
        bufB[t + 768] = o3;
    }
    __syncthreads();
}

// ---------------- forward: LN(q,k) x2 rows; 3 FFTs per 2 rows ----------------
__global__ void __launch_bounds__(256, 3) fft_fwd_kernel(
    const float* __restrict__ gq, const float* __restrict__ betaq,
    const float* __restrict__ gk, const float* __restrict__ betak)
{
    const int row0 = blockIdx.x * 2;
    const int row1 = row0 + 1;
    const int t = threadIdx.x;
    __shared__ float2 tw[768];
    __shared__ float2 bufA[1024];
    __shared__ float2 bufB[1024];
    __shared__ float2 red2[8];

    #pragma unroll
    for (int j = 0; j < 3; j++) {
        int i = t + 256 * j;
        float s_, c_;
        sincospif((float)i * (1.0f/512.0f), &s_, &c_);
        tw[i] = make_float2(c_, -s_);
    }

    const float invN = 1.0f / 1024.0f;
    // LN params (persistent) + normalized q,k in registers (no xv)
    float qn[2][4], kn[2][4];
    #pragma unroll
    for (int r = 0; r < 2; r++) {
        const int row = row0 + r;
        const __half* qr = g_qkh + (size_t)row * 2 * DIMS;
        const __half* kr = qr + DIMS;
        float qv[4], kv[4];
        #pragma unroll
        for (int i = 0; i < 4; i++) {
            int e = t + 256 * i;
            qv[i] = __half2float(qr[e]);
            kv[i] = __half2float(kr[e]);
        }
        float2 s1 = make_float2(0.f, 0.f), s2 = make_float2(0.f, 0.f);
        #pragma unroll
        for (int i = 0; i < 4; i++) {
            s1.x += qv[i]; s1.y += kv[i];
            s2.x += qv[i]*qv[i]; s2.y += kv[i]*kv[i];
        }
        s1 = block_sum2<8>(s1, red2);
        s2 = block_sum2<8>(s2, red2);
        float mq = s1.x * invN, rq = rsqrtf(s2.x * invN - mq*mq + 1e-5f);
        float mk = s1.y * invN, rk = rsqrtf(s2.y * invN - mk*mk + 1e-5f);
        #pragma unroll
        for (int i = 0; i < 4; i++) {
            int e = t + 256 * i;
            qn[r][i] = (qv[i] - mq) * rq * gq[e] + betaq[e];
            kn[r][i] = (kv[i] - mk) * rk * gk[e] + betak[e];
        }
    }

    // FFT of x_r + i*kn_r -> Kx row r (x reloaded fp16 at fill)
    #pragma unroll
    for (int r = 0; r < 2; r++) {
        const int row = row0 + r;
        const __half* xr = g_xh + (size_t)row * DIMS;
        #pragma unroll
        for (int i = 0; i < 4; i++) {
            int e = t + 256 * i;
            bufA[e] = make_float2(__half2float(xr[e]), kn[r][i]);
        }
        __syncthreads();
        fft1024_m3(bufA, bufB, tw, t);
        #pragma unroll
        for (int jj = 0; jj < 2; jj++) {
            int j = t + 256 * jj;
            float2 z  = bufB[j];
            float2 zn = bufB[(1024 - j) & 1023];
            float2 xf = make_float2(0.5f*(z.x + zn.x), 0.5f*(z.y - zn.y));
            float2 df = make_float2(z.x - zn.x, z.y + zn.y);
            float2 kf = make_float2(0.5f*df.y, -0.5f*df.x);
            g_kx[(size_t)row*NF + j] = cmulf(xf, kf);
        }
        if (t == 0) {
            float2 z5 = bufB[512];
            g_kx[(size_t)row*NF + 512] = make_float2(z5.x * z5.y, 0.f);
        }
        __syncthreads();
    }

    // FFT of qn0 + i*qn1 -> Qf rows row0, row1
    #pragma unroll
    for (int i = 0; i < 4; i++) {
        int e = t + 256 * i;
        bufA[e] = make_float2(qn[0][i], qn[1][i]);
    }
    __syncthreads();
    fft1024_m3(bufA, bufB, tw, t);
    #pragma unroll
    for (int jj = 0; jj < 2; jj++) {
        int j = t + 256 * jj;
        float2 z  = bufB[j];
        float2 zn = bufB[(1024 - j) & 1023];
        float2 q0 = make_float2(0.5f*(z.x + zn.x), 0.5f*(z.y - zn.y));
        float2 df = make_float2(z.x - zn.x, z.y + zn.y);
        float2 q1 = make_float2(0.5f*df.y, -0.5f*df.x);
        g_qf[(size_t)row0*NF + j] = q0;
        g_qf[(size_t)row1*NF + j] = q1;
    }
    if (t == 0) {
        float2 z5 = bufB[512];
        g_qf[(size_t)row0*NF + 512] = make_float2(z5.x, 0.f);
        g_qf[(size_t)row1*NF + 512] = make_float2(z5.y, 0.f);
    }
}

// ---------------- reduce S stage 1 + 2 ----------------
__global__ void __launch_bounds__(256) reduce_s1_kernel() {
    const int b  = blockIdx.x;
    const int jc = blockIdx.y;
    const int sc = blockIdx.z;
    const int t  = threadIdx.x;
    const int jl = t & 63;
    const int sl = t >> 6;
    const int j  = jc * 64 + jl;
    float2 acc = make_float2(0.f, 0.f);
    if (j < NF) {
        const int s0 = sc * 128;
        const float2* p = g_kx + (size_t)b * SEQ * NF + (size_t)s0 * NF + j;
        for (int s = sl; s < 128; s += 4) {
            float2 v = p[(size_t)s * NF];
            acc.x += v.x; acc.y += v.y;
        }
    }
    __shared__ float2 red[256];
    red[t] = acc;
    __syncthreads();
    if (t < 128) { red[t].x += red[t+128].x; red[t].y += red[t+128].y; }
    __syncthreads();
    if (t < 64) {
        red[t].x += red[t+64].x; red[t].y += red[t+64].y;
        if (j < NF) g_sp[((size_t)sc * BATCH + b) * NF + j] = red[t];
    }
}
__global__ void __launch_bounds__(64) reduce_s2_kernel() {
    const int b  = blockIdx.x;
    const int jc = blockIdx.y;
    const int j  = jc * 64 + threadIdx.x;
    if (j >= NF) return;
    float2 acc = make_float2(0.f, 0.f);
    #pragma unroll
    for (int sc = 0; sc < SCHUNK; sc++) {
        float2 v = g_sp[((size_t)sc * BATCH + b) * NF + j];
        acc.x += v.x; acc.y += v.y;
    }
    g_sf[b * NF + j] = acc;
}

// ---------------- inverse: 1 FFT per 2 rows; LN(x+mix) x2 -> fp16 x1 ----------------
__global__ void __launch_bounds__(256, 3) fft_inv_ln_kernel(
    const float* __restrict__ g0, const float* __restrict__ beta0)
{
    const int row0 = blockIdx.x * 2;
    const int row1 = row0 + 1;
    const int b = row0 >> 12;
    const int t = threadIdx.x;
    __shared__ float2 tw[768];
    __shared__ float2 bufA[1024];
    __shared__ float2 bufB[1024];
    __shared__ float2 red2[8];

    #pragma unroll
    for (int j = 0; j < 3; j++) {
        int i = t + 256 * j;
        float s_, c_;
        sincospif((float)i * (1.0f/512.0f), &s_, &c_);
        tw[i] = make_float2(c_, -s_);
    }

    #pragma unroll
    for (int jj = 0; jj < 2; jj++) {
        int j = t + 256 * jj;
        float2 sf = g_sf[b*NF + j];
        float2 kx0 = g_kx[(size_t)row0*NF + j];
        float2 qf0 = g_qf[(size_t)row0*NF + j];
        float2 m0 = make_float2(kx0.x + sf.x*qf0.x + sf.y*qf0.y,
                                kx0.y - sf.x*qf0.y + sf.y*qf0.x);
        float2 kx1 = g_kx[(size_t)row1*NF + j];
        float2 qf1 = g_qf[(size_t)row1*NF + j];
        float2 m1 = make_float2(kx1.x + sf.x*qf1.x + sf.y*qf1.y,
                                kx1.y - sf.x*qf1.y + sf.y*qf1.x);
        bufA[j] = make_float2(m0.x - m1.y, -m0.y - m1.x);
        if (j > 0) bufA[1024 - j] = make_float2(m0.x + m1.y, m0.y - m1.x);
    }
    if (t == 0) {
        float2 sf = g_sf[b*NF + 512];
        float2 kx0 = g_kx[(size_t)row0*NF + 512];
        float2 qf0 = g_qf[(size_t)row0*NF + 512];
        float m0 = kx0.x + sf.x*qf0.x;
        float2 kx1 = g_kx[(size_t)row1*NF + 512];
        float2 qf1 = g_qf[(size_t)row1*NF + 512];
        float m1 = kx1.x + sf.x*qf1.x;
        bufA[512] = make_float2(m0, -m1);
    }
    __syncthreads();
    fft1024_m3(bufA, bufB, tw, t);

    const float invN = 1.0f / 1024.0f;
    #pragma unroll
    for (int r = 0; r < 2; r++) {
        const int row = row0 + r;
        const __half* xr = g_xh + (size_t)row * DIMS;
        float y[4];
        float2 s12 = make_float2(0.f, 0.f);
        #pragma unroll
        for (int i = 0; i < 4; i++) {
            int e = t + 256 * i;
            float2 w = bufB[e];
            float mixv = (r == 0 ? w.x : -w.y) * invN;
            y[i] = __half2float(xr[e]) + mixv;
            s12.x += y[i];
            s12.y += y[i] * y[i];
        }
        s12 = block_sum2<8>(s12, red2);
        float m = s12.x * invN, v = s12.y * invN - m*m;
        float rr = rsqrtf(v + 1e-5f);
        __half* oh = g_x1h + (size_t)row * DIMS;
        #pragma unroll
        for (int i = 0; i < 4; i++) {
            int e = t + 256 * i;
            float ov = (y[i] - m) * rr * g0[e] + beta0[e];
            oh[e] = __float2half_rn(ov);
        }
    }
}

// ---------------- out = LN(x1 + ff)  (fp16 in, fused paired reduction) ----------------
__global__ void __launch_bounds__(512) resid_ln_kernel(
    const float* __restrict__ g1v, const float* __restrict__ beta1,
    float* __restrict__ out)
{
    const int row = blockIdx.x;
    const int t = threadIdx.x;
    __shared__ float2 red2[16];
    const __half2* a = (const __half2*)(g_x1h + (size_t)row * DIMS);
    const __half2* f = (const __half2*)(g_ffh + (size_t)row * DIMS);
    float2 av = __half22float2(a[t]);
    float2 fv = __half22float2(f[t]);
    float y0 = av.x + fv.x;
    float y1 = av.y + fv.y;
    const float invN = 1.0f / 1024.0f;
    float2 s12 = block_sum2<16>(make_float2(y0 + y1, y0*y0 + y1*y1), red2);
    float m = s12.x * invN, v = s12.y * invN - m*m;
    float r = rsqrtf(v + 1e-5f);
    float* o = out + (size_t)row * DIMS;
    o[2*t]   = (y0 - m) * r * g1v[2*t]   + beta1[2*t];
    o[2*t+1] = (y1 - m) * r * g1v[2*t+1] + beta1[2*t+1];
}

// ---------------- launch ----------------
extern "C" void kernel_launch(void* const* d_in, const int* in_sizes, int n_in,
                              void* d_out, int out_size)
{
    const float* x     = (const float*)d_in[0];
    const float* Wq    = (const float*)d_in[1];
    const float* bq    = (const float*)d_in[2];
    const float* gq    = (const float*)d_in[3];
    const float* betaq = (const float*)d_in[4];
    const float* Wk    = (const float*)d_in[5];
    const float* bk    = (const float*)d_in[6];
    const float* gk    = (const float*)d_in[7];
    const float* betak = (const float*)d_in[8];
    const float* g0    = (const float*)d_in[9];
    const float* beta0 = (const float*)d_in[10];
    const float* W1    = (const float*)d_in[11];
    const float* b1    = (const float*)d_in[12];
    const float* W2    = (const float*)d_in[13];
    const float* b2    = (const float*)d_in[14];
    const float* g1    = (const float*)d_in[15];
    const float* beta1 = (const float*)d_in[16];
    float* out = (float*)d_out;

    float *pbr;
    __half *pqkh, *px1h, *ph, *pxh, *pwh, *pffh;
    cudaGetSymbolAddress((void**)&pqkh, g_qkh);
    cudaGetSymbolAddress((void**)&px1h, g_x1h);
    cudaGetSymbolAddress((void**)&ph,   g_h);
    cudaGetSymbolAddress((void**)&pffh, g_ffh);
    cudaGetSymbolAddress((void**)&pxh,  g_xh);
    cudaGetSymbolAddress((void**)&pwh,  g_wh);
    cudaGetSymbolAddress((void**)&pbr,  g_br);

    const int SMEM = NSTAGE * STAGE_BYTES;  // 221184 B
    cudaFuncSetAttribute(gemm_h<0,__half>, cudaFuncAttributeMaxDynamicSharedMemorySize, SMEM);
    cudaFuncSetAttribute(gemm_h<1,__half>, cudaFuncAttributeMaxDynamicSharedMemorySize, SMEM);

    // fork: aux stream converts W1/W2 concurrently with G1
    cudaStream_t s1;
    cudaStreamCreate(&s1);
    cudaEvent_t eFork, eW;
    cudaEventCreateWithFlags(&eFork, cudaEventDisableTiming);
    cudaEventCreateWithFlags(&eW,    cudaEventDisableTiming);

    cudaEventRecord(eFork, 0);
    cudaStreamWaitEvent(s1, eFork, 0);
    conv_w_kernel<<<CONVW_BLOCKS, 256, 0, s1>>>(W1, W2, pwh);
    cudaEventRecord(eW, s1);

    // main: x/Wq/Wk conversion + bias pack
    conv_main_kernel<<<CONVM_BLOCKS, 256>>>(x, Wq, Wk, bq, bk, pxh, pwh);

    // [q|k] = x @ [Wq|Wk]^T + [bq|bk]
    gemm_h<0,__half><<<dim3(2*DIMS/128, ROWS/256), 256, SMEM>>>(pxh, pwh + WQK_OFF, pbr, pqkh, 2*DIMS, DIMS);
    // LN(q), LN(k), forward FFTs (merged 3-phase radix-4)
    fft_fwd_kernel<<<ROWS/2, 256>>>(gq, betaq, gk, betak);
    // S = sum_s Kx (two-stage)
    reduce_s1_kernel<<<dim3(BATCH, 9, SCHUNK), 256>>>();
    reduce_s2_kernel<<<dim3(BATCH, 9), 64>>>();
    // mix = irfft x2 rows; x1 = LN(x + mix) -> fp16
    fft_inv_ln_kernel<<<ROWS/2, 256>>>(g0, beta0);
    // h = relu(x1 @ W1^T + b1)
    cudaStreamWaitEvent(0, eW, 0);
    gemm_h<1,__half><<<dim3(FFD/128, ROWS/256), 256, SMEM>>>(px1h, pwh + W1_OFF, b1, ph, FFD, DIMS);
    // ff = h @ W2^T + b2 -> fp16
    gemm_h<0,__half><<<dim3(DIMS/128, ROWS/256), 256, SMEM>>>(ph, pwh + W2_OFF, b2, pffh, DIMS, FFD);
    // out = LN(x1 + ff)
    resid_ln_kernel<<<ROWS, 512>>>(g1, beta1, out);
}